// round 13
// baseline (speedup 1.0000x reference)
#include <cuda_runtime.h>
#include <cuda_bf16.h>
#include <math.h>
#include <stdint.h>

#define BB     2
#define KSTEP  512
#define SDIM   60
#define NACT   5
#define EE     256
#define HH     4
#define DD     64
#define FFD    1024
#define NLAYER 2
#define LL     1536          // 3*KSTEP
#define MTOK   3072          // BB*LL
#define CHUNK  64
#define NCH    24            // LL/CHUNK
#define NBH    8             // BB*HH

#define WTOT   1572864       // total split-weight elements (bf16)
#define PS     68            // padded smem row stride (floats) for attention

// ---------------- scratch (device globals; no allocation) ----------------
__device__ float g_x  [MTOK * EE];
__device__ float g_qkv[MTOK * 3 * EE];
__device__ float g_S  [NBH * NCH * DD * DD];
__device__ float g_ks [NBH * NCH * DD];
__device__ int   g_flag[NLAYER * NBH * NCH];
__device__ int   g_cnt [3 * 48];               // LN-fusion counters (3 uses x 48 row groups)
__device__ __nv_bfloat16 g_xh [MTOK * EE];
__device__ __nv_bfloat16 g_xl [MTOK * EE];
__device__ __nv_bfloat16 g_oh [MTOK * EE];
__device__ __nv_bfloat16 g_ol [MTOK * EE];
__device__ __nv_bfloat16 g_ffh[MTOK * FFD];
__device__ __nv_bfloat16 g_ffl[MTOK * FFD];
__device__ __nv_bfloat16 g_wh [WTOT];
__device__ __nv_bfloat16 g_wl [WTOT];

// ---------------- helpers ----------------------------------------------------
__device__ __forceinline__ uint32_t smem_u32(const void* p) {
    uint32_t a;
    asm("{ .reg .u64 t; cvta.to.shared.u64 t, %1; cvt.u32.u64 %0, t; }" : "=r"(a) : "l"(p));
    return a;
}
__device__ __forceinline__ void cp_async16(uint32_t dst, const void* src) {
    asm volatile("cp.async.cg.shared.global [%0], [%1], 16;" :: "r"(dst), "l"(src) : "memory");
}
__device__ __forceinline__ void cp_commit() { asm volatile("cp.async.commit_group;" ::: "memory"); }

__device__ __forceinline__ void ldsm_x4(uint32_t* r, uint32_t addr) {
    asm volatile("ldmatrix.sync.aligned.m8n8.x4.shared.b16 {%0,%1,%2,%3}, [%4];"
                 : "=r"(r[0]), "=r"(r[1]), "=r"(r[2]), "=r"(r[3]) : "r"(addr));
}
__device__ __forceinline__ void mma_bf16(float* c, const uint32_t* a, const uint32_t* b) {
    asm volatile(
        "mma.sync.aligned.m16n8k16.row.col.f32.bf16.bf16.f32 "
        "{%0,%1,%2,%3}, {%4,%5,%6,%7}, {%8,%9}, {%0,%1,%2,%3};"
        : "+f"(c[0]), "+f"(c[1]), "+f"(c[2]), "+f"(c[3])
        : "r"(a[0]), "r"(a[1]), "r"(a[2]), "r"(a[3]), "r"(b[0]), "r"(b[1]));
}
__device__ __forceinline__ float4 ldcg4(const float* p) {
    float4 v;
    asm volatile("ld.global.cg.v4.f32 {%0,%1,%2,%3}, [%4];"
                 : "=f"(v.x), "=f"(v.y), "=f"(v.z), "=f"(v.w) : "l"(p));
    return v;
}

__device__ __forceinline__ float gelu_exact(float x) {
    return 0.5f * x * (1.0f + erff(x * 0.70710678118654752f));
}

// ---------------- prep: weight split (z<8) + embed+LN1 (z>=8) ---------------
__global__ __launch_bounds__(256) void prep_kernel(
    const float* __restrict__ qkv_w, const float* __restrict__ out_w,
    const float* __restrict__ f1w, const float* __restrict__ f2w,
    __nv_bfloat16* __restrict__ Wh, __nv_bfloat16* __restrict__ Wl,
    const float* __restrict__ rtg, const float* __restrict__ state,
    const float* __restrict__ action,
    const float* __restrict__ rtg_w, const float* __restrict__ rtg_b,
    const float* __restrict__ state_w, const float* __restrict__ state_b,
    const float* __restrict__ action_w, const float* __restrict__ action_b,
    const float* __restrict__ pos,
    const float* __restrict__ g, const float* __restrict__ bta,
    float* __restrict__ x,
    __nv_bfloat16* __restrict__ yh, __nv_bfloat16* __restrict__ yl,
    int* __restrict__ cnt)
{
    int z = blockIdx.z;
    int tid = threadIdx.x;
    if (z < 8) {
        if (z == 0 && blockIdx.x == 0 && blockIdx.y == 0 && tid < 3 * 48)
            cnt[tid] = 0;
        const float* src; int Kd, Nd; size_t doff;
        switch (z) {
            case 0: src = qkv_w;          Kd = 256;  Nd = 768;  doff = 0;       break;
            case 1: src = qkv_w + 196608; Kd = 256;  Nd = 768;  doff = 196608;  break;
            case 2: src = out_w;          Kd = 256;  Nd = 256;  doff = 393216;  break;
            case 3: src = out_w + 65536;  Kd = 256;  Nd = 256;  doff = 458752;  break;
            case 4: src = f1w;            Kd = 256;  Nd = 1024; doff = 524288;  break;
            case 5: src = f1w + 262144;   Kd = 256;  Nd = 1024; doff = 786432;  break;
            case 6: src = f2w;            Kd = 1024; Nd = 256;  doff = 1048576; break;
            default:src = f2w + 262144;   Kd = 1024; Nd = 256;  doff = 1310720; break;
        }
        int nt = blockIdx.x * 32, kt = blockIdx.y * 32;
        if (nt >= Nd || kt >= Kd) return;
        __shared__ float t[32][33];
        int tx = tid & 31, ty = tid >> 5;
#pragma unroll
        for (int i = 0; i < 4; i++) {
            int r = kt + ty + i * 8;
            t[ty + i * 8][tx] = src[(size_t)r * Nd + nt + tx];
        }
        __syncthreads();
#pragma unroll
        for (int i = 0; i < 4; i++) {
            int n = nt + ty + i * 8;
            int k = kt + tx;
            float v = t[tx][ty + i * 8];
            __nv_bfloat16 h = __float2bfloat16(v);
            Wh[doff + (size_t)n * Kd + k] = h;
            Wl[doff + (size_t)n * Kd + k] = __float2bfloat16(v - __bfloat162float(h));
        }
        return;
    }

    int tok = blockIdx.x + blockIdx.y * 32 + (z - 8) * 1024;
    if (tok >= MTOK) return;
    int e   = tid;
    int b   = tok / LL;
    int l   = tok % LL;
    int k   = l / 3;
    int typ = l % 3;
    float acc = pos[k * EE + e];
    if (typ == 0) {
        acc += rtg[b * KSTEP + k] * rtg_w[e] + rtg_b[e];
    } else if (typ == 1) {
        const float* s = state + (b * KSTEP + k) * SDIM;
        float sum = 0.f;
        for (int i = 0; i < SDIM; i++) sum += s[i] * state_w[i * EE + e];
        acc += sum + state_b[e];
    } else {
        const float* a = action + (b * KSTEP + k) * NACT;
        float sum = 0.f;
#pragma unroll
        for (int i = 0; i < NACT; i++) sum += a[i] * action_w[i * EE + e];
        acc += sum + action_b[e];
    }
    x[tok * EE + e] = acc;

    __shared__ float red[8];
    float s = acc;
#pragma unroll
    for (int o = 16; o; o >>= 1) s += __shfl_xor_sync(0xffffffffu, s, o);
    if ((e & 31) == 0) red[e >> 5] = s;
    __syncthreads();
    if (e < 8) {
        float t2 = red[e];
#pragma unroll
        for (int o = 4; o; o >>= 1) t2 += __shfl_xor_sync(0xffu, t2, o);
        if (e == 0) red[0] = t2;
    }
    __syncthreads();
    float mean = red[0] * (1.0f / EE);
    __syncthreads();
    float d  = acc - mean;
    float s2 = d * d;
#pragma unroll
    for (int o = 16; o; o >>= 1) s2 += __shfl_xor_sync(0xffffffffu, s2, o);
    if ((e & 31) == 0) red[e >> 5] = s2;
    __syncthreads();
    if (e < 8) {
        float t2 = red[e];
#pragma unroll
        for (int o = 4; o; o >>= 1) t2 += __shfl_xor_sync(0xffu, t2, o);
        if (e == 0) red[0] = t2;
    }
    __syncthreads();
    float var = red[0] * (1.0f / EE);
    float r = rsqrtf(var + 1e-5f);
    float yv = d * r * g[e] + bta[e];
    __nv_bfloat16 h = __float2bfloat16(yv);
    yh[tok * EE + e] = h;
    yl[tok * EE + e] = __float2bfloat16(yv - __bfloat162float(h));
}

// ---------------- HMMA GEMM: MTx64 tile, BK=64, 2-stage, bf16-split ---------
// EPI: 0 = +bias -> fp32; 1 = gelu(+bias) -> bf16 hi/lo;
//      2 = +bias+Res -> fp32; 3 = EPI2 then fused LN (last block per row group)
// Also zeroes `flags` (192 ints) from block (0,0) when non-null.
template <int MT, int EPI>
__global__ __launch_bounds__(256) void gemm_mma_kernel(
    const __nv_bfloat16* __restrict__ Ah, const __nv_bfloat16* __restrict__ Al,
    const __nv_bfloat16* __restrict__ Bh, const __nv_bfloat16* __restrict__ Bl,
    const float* __restrict__ bias, const float* Res,
    float* Cf, __nv_bfloat16* Ch, __nv_bfloat16* Cl,
    int N, int K, int* flags,
    const float* lng, const float* lnb,
    __nv_bfloat16* yh, __nv_bfloat16* yl, int* cnt)
{
    extern __shared__ char smem[];
    constexpr int THREADS = 256;
    constexpr int RS = 72;                      // 64 elems + 8 pad
    constexpr int A_BYTES = MT * RS * 2;
    constexpr int B_BYTES = 64 * RS * 2;
    constexpr int OFF_AL = A_BYTES;
    constexpr int OFF_BH = 2 * A_BYTES;
    constexpr int SS = 2 * A_BYTES + 2 * B_BYTES;

    uint32_t sb = smem_u32(smem);
    const int tid = threadIdx.x;
    const int m0 = blockIdx.y * MT, n0 = blockIdx.x * 64;

    if (flags && blockIdx.x == 0 && blockIdx.y == 0 && tid < NBH * NCH)
        flags[tid] = 0;

    const int lane = tid & 31, wid = tid >> 5;
    const int wm = (wid >> 1) * (MT / 4);
    const int wn = (wid & 1) * 32;
    const int lr = lane & 15, lc = lane >> 4;

    auto load_stage = [&](int buf, int k0) {
        uint32_t st = sb + buf * SS;
#pragma unroll
        for (int u = tid; u < MT * 8; u += THREADS) {
            int r = u >> 3, c = u & 7;
            uint32_t d = st + (uint32_t)(r * RS + c * 8) * 2;
            cp_async16(d,          Ah + (size_t)(m0 + r) * K + k0 + c * 8);
            cp_async16(d + OFF_AL, Al + (size_t)(m0 + r) * K + k0 + c * 8);
        }
#pragma unroll
        for (int u = tid; u < 512; u += THREADS) {
            int r = u >> 3, c = u & 7;
            uint32_t d = st + OFF_BH + (uint32_t)(r * RS + c * 8) * 2;
            cp_async16(d,           Bh + (size_t)(n0 + r) * K + k0 + c * 8);
            cp_async16(d + B_BYTES, Bl + (size_t)(n0 + r) * K + k0 + c * 8);
        }
    };

    const int NST = K >> 6;
    load_stage(0, 0);
    cp_commit();

    constexpr int MW = (MT == 128) ? 2 : 1;
    float acc[MW][4][4] = {};

    for (int s = 0; s < NST; s++) {
        asm volatile("cp.async.wait_group 0;" ::: "memory");
        __syncthreads();
        if (s + 1 < NST) { load_stage((s + 1) & 1, (s + 1) << 6); cp_commit(); }

        uint32_t st = sb + (s & 1) * SS;
#pragma unroll
        for (int kk = 0; kk < 4; kk++) {
            uint32_t ah[MW][4], al[MW][4], bh[2][4], bl[2][4];
#pragma unroll
            for (int mt = 0; mt < MW; mt++) {
                uint32_t ad = st + (uint32_t)((wm + mt * 16 + lr) * RS + kk * 16 + lc * 8) * 2;
                ldsm_x4(ah[mt], ad);
                ldsm_x4(al[mt], ad + OFF_AL);
            }
#pragma unroll
            for (int np = 0; np < 2; np++) {
                uint32_t bd = st + OFF_BH + (uint32_t)((wn + np * 16 + lr) * RS + kk * 16 + lc * 8) * 2;
                ldsm_x4(bh[np], bd);
                ldsm_x4(bl[np], bd + B_BYTES);
            }
#pragma unroll
            for (int mt = 0; mt < MW; mt++)
#pragma unroll
                for (int nt = 0; nt < 4; nt++) {
                    uint32_t bhp[2] = { bh[nt >> 1][nt & 1], bh[nt >> 1][2 + (nt & 1)] };
                    uint32_t blp[2] = { bl[nt >> 1][nt & 1], bl[nt >> 1][2 + (nt & 1)] };
                    mma_bf16(acc[mt][nt], ah[mt], bhp);
                    mma_bf16(acc[mt][nt], ah[mt], blp);
                    mma_bf16(acc[mt][nt], al[mt], bhp);
                }
        }
    }

    const int tr = lane >> 2;
    const int tc = (lane & 3) * 2;
#pragma unroll
    for (int mt = 0; mt < MW; mt++) {
#pragma unroll
        for (int nt = 0; nt < 4; nt++) {
            int col = n0 + wn + nt * 8 + tc;
            float b0 = bias[col], b1 = bias[col + 1];
#pragma unroll
            for (int half = 0; half < 2; half++) {
                int row = m0 + wm + mt * 16 + tr + half * 8;
                float v0 = acc[mt][nt][half * 2]     + b0;
                float v1 = acc[mt][nt][half * 2 + 1] + b1;
                if (EPI == 1) {
                    v0 = gelu_exact(v0);
                    v1 = gelu_exact(v1);
                    __nv_bfloat16 h0 = __float2bfloat16(v0);
                    __nv_bfloat16 h1 = __float2bfloat16(v1);
                    __nv_bfloat162 hp; hp.x = h0; hp.y = h1;
                    __nv_bfloat162 lp;
                    lp.x = __float2bfloat16(v0 - __bfloat162float(h0));
                    lp.y = __float2bfloat16(v1 - __bfloat162float(h1));
                    *(__nv_bfloat162*)&Ch[(size_t)row * N + col] = hp;
                    *(__nv_bfloat162*)&Cl[(size_t)row * N + col] = lp;
                } else {
                    if (EPI >= 2) {
                        float2 rv = *(const float2*)&Res[(size_t)row * N + col];
                        v0 += rv.x; v1 += rv.y;
                    }
                    float2 ov; ov.x = v0; ov.y = v1;
                    *(float2*)&Cf[(size_t)row * N + col] = ov;
                }
            }
        }
    }

    // ---- EPI 3: fused LayerNorm by the last-finishing block of this row group
    if (EPI == 3) {
        __shared__ int lastf;
        __syncthreads();
        if (tid == 0) {
            __threadfence();
            int old = atomicAdd(&cnt[blockIdx.y], 1);
            lastf = (old == 3);
        }
        __syncthreads();
        if (lastf) {
            __threadfence();
            int r  = m0 + (tid >> 2);
            int c0 = (tid & 3) * 64;
            const float* xr = Cf + (size_t)r * EE + c0;
            float s = 0.f, s2 = 0.f;
#pragma unroll
            for (int i = 0; i < 16; i++) {
                float4 v = ldcg4(xr + i * 4);
                s  += v.x + v.y + v.z + v.w;
                s2 += v.x * v.x + v.y * v.y + v.z * v.z + v.w * v.w;
            }
            s  += __shfl_xor_sync(0xffffffffu, s, 1);
            s  += __shfl_xor_sync(0xffffffffu, s, 2);
            s2 += __shfl_xor_sync(0xffffffffu, s2, 1);
            s2 += __shfl_xor_sync(0xffffffffu, s2, 2);
            float mean = s * (1.0f / EE);
            float rstd = rsqrtf(s2 * (1.0f / EE) - mean * mean + 1e-5f);
#pragma unroll
            for (int i = 0; i < 16; i++) {
                float4 v  = ldcg4(xr + i * 4);
                float4 gv = *(const float4*)&lng[c0 + i * 4];
                float4 bv = *(const float4*)&lnb[c0 + i * 4];
                float y0 = (v.x - mean) * rstd * gv.x + bv.x;
                float y1 = (v.y - mean) * rstd * gv.y + bv.y;
                float y2 = (v.z - mean) * rstd * gv.z + bv.z;
                float y3 = (v.w - mean) * rstd * gv.w + bv.w;
                __nv_bfloat16 h0 = __float2bfloat16(y0), h1 = __float2bfloat16(y1);
                __nv_bfloat16 h2 = __float2bfloat16(y2), h3 = __float2bfloat16(y3);
                __nv_bfloat162 hp0; hp0.x = h0; hp0.y = h1;
                __nv_bfloat162 hp1; hp1.x = h2; hp1.y = h3;
                __nv_bfloat162 lp0, lp1;
                lp0.x = __float2bfloat16(y0 - __bfloat162float(h0));
                lp0.y = __float2bfloat16(y1 - __bfloat162float(h1));
                lp1.x = __float2bfloat16(y2 - __bfloat162float(h2));
                lp1.y = __float2bfloat16(y3 - __bfloat162float(h3));
                uint2 hh, ll;
                hh.x = *(uint32_t*)&hp0; hh.y = *(uint32_t*)&hp1;
                ll.x = *(uint32_t*)&lp0; ll.y = *(uint32_t*)&lp1;
                size_t idx = (size_t)r * EE + c0 + i * 4;
                *(uint2*)&yh[idx] = hh;
                *(uint2*)&yl[idx] = ll;
            }
        }
    }
}

// ---------------- fused attention: chunk sums + lookback prefix + output ----
__global__ __launch_bounds__(256) void attn_fused_kernel(
    const float* __restrict__ qkv, float* __restrict__ S,
    float* __restrict__ ks, int* __restrict__ flags,
    __nv_bfloat16* __restrict__ oh, __nv_bfloat16* __restrict__ ol)
{
    extern __shared__ float sm[];
    float* Ks   = sm;
    float* Vs   = sm + 64  * PS;
    float* Qs   = sm + 128 * PS;
    float* Psh  = sm + 192 * PS;
    float* As   = sm + 256 * PS;
    float* dens = sm + 320 * PS;
    float* kps  = dens + 64;

    const int blk = blockIdx.x;
    const int bh = blk / NCH, c = blk % NCH;
    const int b = bh / HH, h = bh % HH;
    const int tid = threadIdx.x;
    const int d0 = (tid >> 4) * 4, e0 = (tid & 15) * 4;

#pragma unroll
    for (int i = tid; i < 4096; i += 256) {
        int t = i >> 6, d = i & 63;
        int row = b * LL + c * CHUNK + t;
        float kv = qkv[row * 768 + 256 + h * 64 + d];
        Ks[t * PS + d] = fmaxf(kv, 0.f) + 1e-6f;
        Vs[t * PS + d] = qkv[row * 768 + 512 + h * 64 + d];
    }
    __syncthreads();

    {
        float sc[4][4] = {};
#pragma unroll 4
        for (int t = 0; t < 64; t++) {
            float kd[4], ve[4];
            *(float4*)kd = *(const float4*)&Ks[t * PS + d0];
            *(float4*)ve = *(const float4*)&Vs[t * PS + e0];
#pragma unroll
            for (int i = 0; i < 4; i++)
#pragma unroll
                for (int j = 0; j < 4; j++)
                    sc[i][j] += kd[i] * ve[j];
        }
        float* So = S + (size_t)blk * 4096;
#pragma unroll
        for (int i = 0; i < 4; i++)
            *(float4*)&So[(d0 + i) * 64 + e0] =
                make_float4(sc[i][0], sc[i][1], sc[i][2], sc[i][3]);
        if (tid < 64) {
            float s = 0.f;
#pragma unroll 8
            for (int t = 0; t < 64; t++) s += Ks[t * PS + tid];
            ks[blk * 64 + tid] = s;
        }
    }
    __syncthreads();
    if (tid == 0) { __threadfence(); atomicExch(&flags[blk], 1); }

#pragma unroll
    for (int i = tid; i < 4096; i += 256) {
        int t = i >> 6, d = i & 63;
        int row = b * LL + c * CHUNK + t;
        float qv = qkv[row * 768 + h * 64 + d];
        Qs[t * PS + d] = fmaxf(qv, 0.f) + 1e-6f;
    }

    if (tid < c) {
        while (atomicAdd(&flags[bh * NCH + tid], 0) == 0) { __nanosleep(60); }
        __threadfence();
    }
    __syncthreads();

    {
        float pr[4][4] = {};
        for (int cc = 0; cc < c; cc++) {
            const float* Sp = S + (size_t)(bh * NCH + cc) * 4096;
#pragma unroll
            for (int i = 0; i < 4; i++) {
                float4 v = *(const float4*)&Sp[(d0 + i) * 64 + e0];
                pr[i][0] += v.x; pr[i][1] += v.y; pr[i][2] += v.z; pr[i][3] += v.w;
            }
        }
#pragma unroll
        for (int i = 0; i < 4; i++)
            *(float4*)&Psh[(d0 + i) * PS + e0] =
                make_float4(pr[i][0], pr[i][1], pr[i][2], pr[i][3]);
        if (tid < 64) {
            float s = 0.f;
            for (int cc = 0; cc < c; cc++) s += ks[(bh * NCH + cc) * 64 + tid];
            kps[tid] = s;
        }
    }
    __syncthreads();

    const int i0 = d0, j0 = e0;
    float acc[4][4] = {};

#pragma unroll 2
    for (int d = 0; d < 64; d += 4) {
        float qv[4][4], pv[4][4];
#pragma unroll
        for (int i = 0; i < 4; i++)
            *(float4*)qv[i] = *(const float4*)&Qs[(i0 + i) * PS + d];
#pragma unroll
        for (int dd = 0; dd < 4; dd++)
            *(float4*)pv[dd] = *(const float4*)&Psh[(d + dd) * PS + j0];
#pragma unroll
        for (int i = 0; i < 4; i++)
#pragma unroll
            for (int j = 0; j < 4; j++)
#pragma unroll
                for (int dd = 0; dd < 4; dd++)
                    acc[i][j] += qv[i][dd] * pv[dd][j];
    }
    if (tid < 64) {
        float s = 0.f;
#pragma unroll
        for (int d = 0; d < 64; d += 4) {
            float4 q4 = *(const float4*)&Qs[tid * PS + d];
            float4 k4 = *(const float4*)&kps[d];
            s += q4.x * k4.x + q4.y * k4.y + q4.z * k4.z + q4.w * k4.w;
        }
        dens[tid] = s;
    }

    {
        float av[4][4] = {};
#pragma unroll 2
        for (int d = 0; d < 64; d += 4) {
            float qv[4][4], kv[4][4];
#pragma unroll
            for (int i = 0; i < 4; i++)
                *(float4*)qv[i] = *(const float4*)&Qs[(i0 + i) * PS + d];
#pragma unroll
            for (int j = 0; j < 4; j++)
                *(float4*)kv[j] = *(const float4*)&Ks[(j0 + j) * PS + d];
#pragma unroll
            for (int i = 0; i < 4; i++)
#pragma unroll
                for (int j = 0; j < 4; j++)
#pragma unroll
                    for (int dd = 0; dd < 4; dd++)
                        av[i][j] += qv[i][dd] * kv[j][dd];
        }
#pragma unroll
        for (int i = 0; i < 4; i++) {
            float4 o;
            o.x = (j0 + 0 <= i0 + i) ? av[i][0] : 0.f;
            o.y = (j0 + 1 <= i0 + i) ? av[i][1] : 0.f;
            o.z = (j0 + 2 <= i0 + i) ? av[i][2] : 0.f;
            o.w = (j0 + 3 <= i0 + i) ? av[i][3] : 0.f;
            *(float4*)&As[(i0 + i) * PS + j0] = o;
        }
    }
    __syncthreads();

    if (tid < 64) {
        float rs = 0.f;
#pragma unroll
        for (int j = 0; j < 64; j += 4) {
            float4 a4 = *(const float4*)&As[tid * PS + j];
            rs += a4.x + a4.y + a4.z + a4.w;
        }
        dens[tid] += rs;
    }
    __syncthreads();

#pragma unroll 2
    for (int j = 0; j < 64; j += 4) {
        float av[4][4], vv[4][4];
#pragma unroll
        for (int i = 0; i < 4; i++)
            *(float4*)av[i] = *(const float4*)&As[(i0 + i) * PS + j];
#pragma unroll
        for (int m = 0; m < 4; m++)
            *(float4*)vv[m] = *(const float4*)&Vs[(j + m) * PS + j0];
#pragma unroll
        for (int i = 0; i < 4; i++)
#pragma unroll
            for (int jj = 0; jj < 4; jj++)
#pragma unroll
                for (int m = 0; m < 4; m++)
                    acc[i][jj] += av[i][m] * vv[m][jj];
    }

#pragma unroll
    for (int i = 0; i < 4; i++) {
        float dn = fmaxf(dens[i0 + i], 1e-6f);
        int row = b * LL + c * CHUNK + i0 + i;
        float inv = 1.0f / dn;
        size_t idx = (size_t)row * EE + h * 64 + j0;
        __nv_bfloat162 hp0, hp1, lp0, lp1;
        float v0 = acc[i][0] * inv, v1 = acc[i][1] * inv;
        float v2 = acc[i][2] * inv, v3 = acc[i][3] * inv;
        __nv_bfloat16 h0 = __float2bfloat16(v0), h1 = __float2bfloat16(v1);
        __nv_bfloat16 h2 = __float2bfloat16(v2), h3 = __float2bfloat16(v3);
        hp0.x = h0; hp0.y = h1; hp1.x = h2; hp1.y = h3;
        lp0.x = __float2bfloat16(v0 - __bfloat162float(h0));
        lp0.y = __float2bfloat16(v1 - __bfloat162float(h1));
        lp1.x = __float2bfloat16(v2 - __bfloat162float(h2));
        lp1.y = __float2bfloat16(v3 - __bfloat162float(h3));
        uint2 hh, ll;
        hh.x = *(uint32_t*)&hp0; hh.y = *(uint32_t*)&hp1;
        ll.x = *(uint32_t*)&lp0; ll.y = *(uint32_t*)&lp1;
        *(uint2*)&oh[idx] = hh;
        *(uint2*)&ol[idx] = ll;
    }
}

// ---------------- final LN + pred fused -------------------------------------
__global__ __launch_bounds__(256) void predln_kernel(
    const float* __restrict__ x, const float* __restrict__ g,
    const float* __restrict__ bta,
    const float* __restrict__ pred_w, const float* __restrict__ pred_b,
    float* __restrict__ out)
{
    int bk = blockIdx.x;
    int b = bk / KSTEP, k = bk % KSTEP;
    int row = b * LL + 3 * k + 1;
    int e = threadIdx.x;
    __shared__ float red[8];
    __shared__ float ys[EE];

    float v = x[(size_t)row * EE + e];
    float s = v;
#pragma unroll
    for (int o = 16; o; o >>= 1) s += __shfl_xor_sync(0xffffffffu, s, o);
    if ((e & 31) == 0) red[e >> 5] = s;
    __syncthreads();
    if (e < 8) {
        float t = red[e];
#pragma unroll
        for (int o = 4; o; o >>= 1) t += __shfl_xor_sync(0xffu, t, o);
        if (e == 0) red[0] = t;
    }
    __syncthreads();
    float mean = red[0] * (1.0f / EE);
    __syncthreads();
    float d = v - mean;
    float s2 = d * d;
#pragma unroll
    for (int o = 16; o; o >>= 1) s2 += __shfl_xor_sync(0xffffffffu, s2, o);
    if ((e & 31) == 0) red[e >> 5] = s2;
    __syncthreads();
    if (e < 8) {
        float t = red[e];
#pragma unroll
        for (int o = 4; o; o >>= 1) t += __shfl_xor_sync(0xffu, t, o);
        if (e == 0) red[0] = t;
    }
    __syncthreads();
    float var = red[0] * (1.0f / EE);
    float r = rsqrtf(var + 1e-5f);
    ys[e] = d * r * g[e] + bta[e];
    __syncthreads();

    int w = e >> 5, lane = e & 31;
    if (w < NACT) {
        float sum = 0.f;
        for (int i = lane; i < EE; i += 32) sum += ys[i] * pred_w[i * NACT + w];
#pragma unroll
        for (int o = 16; o; o >>= 1) sum += __shfl_xor_sync(0xffffffffu, sum, o);
        if (lane == 0) out[bk * NACT + w] = sum + pred_b[w];
    }
}

// ---------------- launch ----------------------------------------------------
extern "C" void kernel_launch(void* const* d_in, const int* in_sizes, int n_in,
                              void* d_out, int out_size)
{
    const float* rtg      = (const float*)d_in[0];
    const float* state    = (const float*)d_in[1];
    const float* action   = (const float*)d_in[2];
    const float* rtg_w    = (const float*)d_in[3];
    const float* rtg_b    = (const float*)d_in[4];
    const float* state_w  = (const float*)d_in[5];
    const float* state_b  = (const float*)d_in[6];
    const float* action_w = (const float*)d_in[7];
    const float* action_b = (const float*)d_in[8];
    const float* pos_emb  = (const float*)d_in[9];
    const float* norm1_g  = (const float*)d_in[10];
    const float* norm1_b  = (const float*)d_in[11];
    const float* qkv_w    = (const float*)d_in[12];
    const float* qkv_b    = (const float*)d_in[13];
    const float* out_w    = (const float*)d_in[14];
    const float* out_b    = (const float*)d_in[15];
    const float* norm2_g  = (const float*)d_in[16];
    const float* norm2_b  = (const float*)d_in[17];
    const float* ffn1_w   = (const float*)d_in[18];
    const float* ffn1_b   = (const float*)d_in[19];
    const float* ffn2_w   = (const float*)d_in[20];
    const float* ffn2_b   = (const float*)d_in[21];
    const float* normf_g  = (const float*)d_in[22];
    const float* normf_b  = (const float*)d_in[23];
    const float* pred_w   = (const float*)d_in[24];
    const float* pred_b   = (const float*)d_in[25];

    float *x, *qkv, *S, *ks;
    int *flags, *cnt;
    __nv_bfloat16 *xh, *xl, *oh, *ol, *ffh, *ffl, *wh, *wl;
    cudaGetSymbolAddress((void**)&x,     g_x);
    cudaGetSymbolAddress((void**)&qkv,   g_qkv);
    cudaGetSymbolAddress((void**)&S,     g_S);
    cudaGetSymbolAddress((void**)&ks,    g_ks);
    cudaGetSymbolAddress((void**)&flags, g_flag);
    cudaGetSymbolAddress((void**)&cnt,   g_cnt);
    cudaGetSymbolAddress((void**)&xh,    g_xh);
    cudaGetSymbolAddress((void**)&xl,    g_xl);
    cudaGetSymbolAddress((void**)&oh,    g_oh);
    cudaGetSymbolAddress((void**)&ol,    g_ol);
    cudaGetSymbolAddress((void**)&ffh,   g_ffh);
    cudaGetSymbolAddress((void**)&ffl,   g_ffl);
    cudaGetSymbolAddress((void**)&wh,    g_wh);
    cudaGetSymbolAddress((void**)&wl,    g_wl);

    const int SMEM_ATT  = (320 * PS + 128) * sizeof(float);        // 87552
    const int SMEM_G128 = 2 * (2 * 128 * 72 * 2 + 2 * 64 * 72 * 2); // 110592
    const int SMEM_G64  = 2 * (4 * 64 * 72 * 2);                    // 73728
    cudaFuncSetAttribute(attn_fused_kernel,
                         cudaFuncAttributeMaxDynamicSharedMemorySize, SMEM_ATT);
    cudaFuncSetAttribute((const void*)gemm_mma_kernel<128, 0>,
                         cudaFuncAttributeMaxDynamicSharedMemorySize, SMEM_G128);
    cudaFuncSetAttribute((const void*)gemm_mma_kernel<128, 1>,
                         cudaFuncAttributeMaxDynamicSharedMemorySize, SMEM_G128);
    cudaFuncSetAttribute((const void*)gemm_mma_kernel<64, 2>,
                         cudaFuncAttributeMaxDynamicSharedMemorySize, SMEM_G64);
    cudaFuncSetAttribute((const void*)gemm_mma_kernel<64, 3>,
                         cudaFuncAttributeMaxDynamicSharedMemorySize, SMEM_G64);

    prep_kernel<<<dim3(32, 32, 11), 256>>>(
        qkv_w, out_w, ffn1_w, ffn2_w, wh, wl,
        rtg, state, action, rtg_w, rtg_b, state_w, state_b,
        action_w, action_b, pos_emb, norm1_g, norm1_b, x, xh, xl, cnt);

    for (int layer = 0; layer < NLAYER; layer++) {
        const float* n2g = norm2_g + layer * EE;
        const float* n2b = norm2_b + layer * EE;
        const float* qb  = qkv_b  + layer * 3 * EE;
        const float* ob  = out_b  + layer * EE;
        const float* f1b = ffn1_b + layer * FFD;
        const float* f2b = ffn2_b + layer * EE;
        size_t qoff  = (size_t)layer * 196608;
        size_t ooff  = 393216  + (size_t)layer * 65536;
        size_t f1off = 524288  + (size_t)layer * 262144;
        size_t f2off = 1048576 + (size_t)layer * 262144;
        int* lflags = flags + layer * NBH * NCH;

        // qkv: LN'd input already in xh/xl (prep or fused LN from previous GEMM)
        gemm_mma_kernel<128, 0><<<dim3(12, 24), 256, SMEM_G128>>>(
            xh, xl, wh + qoff, wl + qoff, qb, nullptr, qkv, nullptr, nullptr,
            768, 256, lflags, nullptr, nullptr, nullptr, nullptr, nullptr);

        attn_fused_kernel<<<NBH * NCH, 256, SMEM_ATT>>>(qkv, S, ks, lflags, oh, ol);

        // out proj + bias + residual -> x, fused LN2 -> xh/xl
        gemm_mma_kernel<64, 3><<<dim3(4, 48), 256, SMEM_G64>>>(
            oh, ol, wh + ooff, wl + ooff, ob, x, x, nullptr, nullptr,
            256, 256, nullptr, n2g, n2b, xh, xl, cnt + layer * 2 * 48);

        // ffn1 (reads LN2'd xh/xl)
        gemm_mma_kernel<128, 1><<<dim3(16, 24), 256, SMEM_G128>>>(
            xh, xl, wh + f1off, wl + f1off, f1b, nullptr, nullptr, ffh, ffl,
            1024, 256, nullptr, nullptr, nullptr, nullptr, nullptr, nullptr);

        // ffn2 + bias + residual -> x; layer 0 fuses next layer's LN1
        if (layer == 0) {
            gemm_mma_kernel<64, 3><<<dim3(4, 48), 256, SMEM_G64>>>(
                ffh, ffl, wh + f2off, wl + f2off, f2b, x, x, nullptr, nullptr,
                256, 1024, nullptr, norm1_g + EE, norm1_b + EE, xh, xl, cnt + 48);
        } else {
            gemm_mma_kernel<64, 2><<<dim3(4, 48), 256, SMEM_G64>>>(
                ffh, ffl, wh + f2off, wl + f2off, f2b, x, x, nullptr, nullptr,
                256, 1024, nullptr, nullptr, nullptr, nullptr, nullptr, nullptr);
        }
    }

    predln_kernel<<<BB * KSTEP, 256>>>(x, normf_g, normf_b, pred_w, pred_b,
                                       (float*)d_out);
}

// round 14
// speedup vs baseline: 1.3032x; 1.3032x over previous
#include <cuda_runtime.h>
#include <cuda_bf16.h>
#include <math.h>
#include <stdint.h>

#define BB     2
#define KSTEP  512
#define SDIM   60
#define NACT   5
#define EE     256
#define HH     4
#define DD     64
#define FFD    1024
#define NLAYER 2
#define LL     1536          // 3*KSTEP
#define MTOK   3072          // BB*LL
#define CHUNK  64
#define NCH    24            // LL/CHUNK
#define NBH    8             // BB*HH

#define WTOT   1572864       // total split-weight elements (bf16)
#define PS     68            // padded smem row stride (floats) for attention

// ---------------- scratch (device globals; no allocation) ----------------
__device__ float g_x  [MTOK * EE];
__device__ float g_xn [MTOK * EE];
__device__ float g_qkv[MTOK * 3 * EE];
__device__ float g_S  [NBH * NCH * DD * DD];
__device__ float g_ks [NBH * NCH * DD];
__device__ int   g_flag[NLAYER * NBH * NCH];
__device__ __nv_bfloat16 g_xh [MTOK * EE];
__device__ __nv_bfloat16 g_xl [MTOK * EE];
__device__ __nv_bfloat16 g_oh [MTOK * EE];
__device__ __nv_bfloat16 g_ol [MTOK * EE];
__device__ __nv_bfloat16 g_ffh[MTOK * FFD];
__device__ __nv_bfloat16 g_ffl[MTOK * FFD];
__device__ __nv_bfloat16 g_wh [WTOT];
__device__ __nv_bfloat16 g_wl [WTOT];

// ---------------- helpers ----------------------------------------------------
__device__ __forceinline__ uint32_t smem_u32(const void* p) {
    uint32_t a;
    asm("{ .reg .u64 t; cvta.to.shared.u64 t, %1; cvt.u32.u64 %0, t; }" : "=r"(a) : "l"(p));
    return a;
}
__device__ __forceinline__ void cp_async16(uint32_t dst, const void* src) {
    asm volatile("cp.async.cg.shared.global [%0], [%1], 16;" :: "r"(dst), "l"(src) : "memory");
}
__device__ __forceinline__ void cp_commit() { asm volatile("cp.async.commit_group;" ::: "memory"); }

__device__ __forceinline__ void ldsm_x4(uint32_t* r, uint32_t addr) {
    asm volatile("ldmatrix.sync.aligned.m8n8.x4.shared.b16 {%0,%1,%2,%3}, [%4];"
                 : "=r"(r[0]), "=r"(r[1]), "=r"(r[2]), "=r"(r[3]) : "r"(addr));
}
__device__ __forceinline__ void mma_bf16(float* c, const uint32_t* a, const uint32_t* b) {
    asm volatile(
        "mma.sync.aligned.m16n8k16.row.col.f32.bf16.bf16.f32 "
        "{%0,%1,%2,%3}, {%4,%5,%6,%7}, {%8,%9}, {%0,%1,%2,%3};"
        : "+f"(c[0]), "+f"(c[1]), "+f"(c[2]), "+f"(c[3])
        : "r"(a[0]), "r"(a[1]), "r"(a[2]), "r"(a[3]), "r"(b[0]), "r"(b[1]));
}

__device__ __forceinline__ float gelu_exact(float x) {
    return 0.5f * x * (1.0f + erff(x * 0.70710678118654752f));
}

// ---------------- prep: weight split (z<8) + embed+LN1 (z>=8) ---------------
__global__ __launch_bounds__(256) void prep_kernel(
    const float* __restrict__ qkv_w, const float* __restrict__ out_w,
    const float* __restrict__ f1w, const float* __restrict__ f2w,
    __nv_bfloat16* __restrict__ Wh, __nv_bfloat16* __restrict__ Wl,
    const float* __restrict__ rtg, const float* __restrict__ state,
    const float* __restrict__ action,
    const float* __restrict__ rtg_w, const float* __restrict__ rtg_b,
    const float* __restrict__ state_w, const float* __restrict__ state_b,
    const float* __restrict__ action_w, const float* __restrict__ action_b,
    const float* __restrict__ pos,
    const float* __restrict__ g, const float* __restrict__ bta,
    float* __restrict__ x,
    __nv_bfloat16* __restrict__ yh, __nv_bfloat16* __restrict__ yl)
{
    int z = blockIdx.z;
    int tid = threadIdx.x;
    if (z < 8) {
        const float* src; int Kd, Nd; size_t doff;
        switch (z) {
            case 0: src = qkv_w;          Kd = 256;  Nd = 768;  doff = 0;       break;
            case 1: src = qkv_w + 196608; Kd = 256;  Nd = 768;  doff = 196608;  break;
            case 2: src = out_w;          Kd = 256;  Nd = 256;  doff = 393216;  break;
            case 3: src = out_w + 65536;  Kd = 256;  Nd = 256;  doff = 458752;  break;
            case 4: src = f1w;            Kd = 256;  Nd = 1024; doff = 524288;  break;
            case 5: src = f1w + 262144;   Kd = 256;  Nd = 1024; doff = 786432;  break;
            case 6: src = f2w;            Kd = 1024; Nd = 256;  doff = 1048576; break;
            default:src = f2w + 262144;   Kd = 1024; Nd = 256;  doff = 1310720; break;
        }
        int nt = blockIdx.x * 32, kt = blockIdx.y * 32;
        if (nt >= Nd || kt >= Kd) return;
        __shared__ float t[32][33];
        int tx = tid & 31, ty = tid >> 5;
#pragma unroll
        for (int i = 0; i < 4; i++) {
            int r = kt + ty + i * 8;
            t[ty + i * 8][tx] = src[(size_t)r * Nd + nt + tx];
        }
        __syncthreads();
#pragma unroll
        for (int i = 0; i < 4; i++) {
            int n = nt + ty + i * 8;
            int k = kt + tx;
            float v = t[tx][ty + i * 8];
            __nv_bfloat16 h = __float2bfloat16(v);
            Wh[doff + (size_t)n * Kd + k] = h;
            Wl[doff + (size_t)n * Kd + k] = __float2bfloat16(v - __bfloat162float(h));
        }
        return;
    }

    int tok = blockIdx.x + blockIdx.y * 32 + (z - 8) * 1024;
    if (tok >= MTOK) return;
    int e   = tid;
    int b   = tok / LL;
    int l   = tok % LL;
    int k   = l / 3;
    int typ = l % 3;
    float acc = pos[k * EE + e];
    if (typ == 0) {
        acc += rtg[b * KSTEP + k] * rtg_w[e] + rtg_b[e];
    } else if (typ == 1) {
        const float* s = state + (b * KSTEP + k) * SDIM;
        float sum = 0.f;
        for (int i = 0; i < SDIM; i++) sum += s[i] * state_w[i * EE + e];
        acc += sum + state_b[e];
    } else {
        const float* a = action + (b * KSTEP + k) * NACT;
        float sum = 0.f;
#pragma unroll
        for (int i = 0; i < NACT; i++) sum += a[i] * action_w[i * EE + e];
        acc += sum + action_b[e];
    }
    x[tok * EE + e] = acc;

    __shared__ float red[8];
    float s = acc;
#pragma unroll
    for (int o = 16; o; o >>= 1) s += __shfl_xor_sync(0xffffffffu, s, o);
    if ((e & 31) == 0) red[e >> 5] = s;
    __syncthreads();
    if (e < 8) {
        float t2 = red[e];
#pragma unroll
        for (int o = 4; o; o >>= 1) t2 += __shfl_xor_sync(0xffu, t2, o);
        if (e == 0) red[0] = t2;
    }
    __syncthreads();
    float mean = red[0] * (1.0f / EE);
    __syncthreads();
    float d  = acc - mean;
    float s2 = d * d;
#pragma unroll
    for (int o = 16; o; o >>= 1) s2 += __shfl_xor_sync(0xffffffffu, s2, o);
    if ((e & 31) == 0) red[e >> 5] = s2;
    __syncthreads();
    if (e < 8) {
        float t2 = red[e];
#pragma unroll
        for (int o = 4; o; o >>= 1) t2 += __shfl_xor_sync(0xffu, t2, o);
        if (e == 0) red[0] = t2;
    }
    __syncthreads();
    float var = red[0] * (1.0f / EE);
    float r = rsqrtf(var + 1e-5f);
    float yv = d * r * g[e] + bta[e];
    __nv_bfloat16 h = __float2bfloat16(yv);
    yh[tok * EE + e] = h;
    yl[tok * EE + e] = __float2bfloat16(yv - __bfloat162float(h));
}

// ---------------- LayerNorm: 4 rows/block, float4 ---------------------------
__global__ __launch_bounds__(256) void ln4_kernel(
    const float* __restrict__ x, const float* __restrict__ g,
    const float* __restrict__ bta, float* __restrict__ y,
    __nv_bfloat16* __restrict__ yh, __nv_bfloat16* __restrict__ yl)
{
    __shared__ float red[16];
    int tid = threadIdx.x;
    int r   = tid >> 6;
    int l64 = tid & 63;
    int w   = tid >> 5;
    int lane = tid & 31;
    int row = blockIdx.x * 4 + r;
    size_t base = (size_t)row * EE + l64 * 4;

    float4 v = *(const float4*)&x[base];
    float s = v.x + v.y + v.z + v.w;
#pragma unroll
    for (int o = 16; o; o >>= 1) s += __shfl_xor_sync(0xffffffffu, s, o);
    if (lane == 0) red[w] = s;
    __syncthreads();
    float mean = (red[2 * r] + red[2 * r + 1]) * (1.0f / EE);

    float4 d;
    d.x = v.x - mean; d.y = v.y - mean; d.z = v.z - mean; d.w = v.w - mean;
    float s2 = d.x * d.x + d.y * d.y + d.z * d.z + d.w * d.w;
#pragma unroll
    for (int o = 16; o; o >>= 1) s2 += __shfl_xor_sync(0xffffffffu, s2, o);
    if (lane == 0) red[8 + w] = s2;
    __syncthreads();
    float var = (red[8 + 2 * r] + red[8 + 2 * r + 1]) * (1.0f / EE);
    float rs = rsqrtf(var + 1e-5f);

    float4 gv = *(const float4*)&g[l64 * 4];
    float4 bv = *(const float4*)&bta[l64 * 4];
    float4 o;
    o.x = d.x * rs * gv.x + bv.x;
    o.y = d.y * rs * gv.y + bv.y;
    o.z = d.z * rs * gv.z + bv.z;
    o.w = d.w * rs * gv.w + bv.w;
    *(float4*)&y[base] = o;

    __nv_bfloat16 h0 = __float2bfloat16(o.x), h1 = __float2bfloat16(o.y);
    __nv_bfloat16 h2 = __float2bfloat16(o.z), h3 = __float2bfloat16(o.w);
    __nv_bfloat162 hp0; hp0.x = h0; hp0.y = h1;
    __nv_bfloat162 hp1; hp1.x = h2; hp1.y = h3;
    __nv_bfloat162 lp0, lp1;
    lp0.x = __float2bfloat16(o.x - __bfloat162float(h0));
    lp0.y = __float2bfloat16(o.y - __bfloat162float(h1));
    lp1.x = __float2bfloat16(o.z - __bfloat162float(h2));
    lp1.y = __float2bfloat16(o.w - __bfloat162float(h3));
    uint2 hh, ll;
    hh.x = *(uint32_t*)&hp0; hh.y = *(uint32_t*)&hp1;
    ll.x = *(uint32_t*)&lp0; ll.y = *(uint32_t*)&lp1;
    *(uint2*)&yh[base] = hh;
    *(uint2*)&yl[base] = ll;
}

// ---------------- HMMA GEMM: MTx64 tile, BK=64, 2-stage, bf16-split ---------
// MT=128: 8 warps 4m x 2n (32x32/warp). MT=64: 8 warps 4m x 2n (16x32/warp).
// Also zeroes `flags` (192 ints) from block (0,0) when non-null.
template <int MT, int EPI>
__global__ __launch_bounds__(256) void gemm_mma_kernel(
    const __nv_bfloat16* __restrict__ Ah, const __nv_bfloat16* __restrict__ Al,
    const __nv_bfloat16* __restrict__ Bh, const __nv_bfloat16* __restrict__ Bl,
    const float* __restrict__ bias, const float* Res,
    float* Cf, __nv_bfloat16* Ch, __nv_bfloat16* Cl,
    int N, int K, int* flags)
{
    extern __shared__ char smem[];
    constexpr int THREADS = 256;
    constexpr int RS = 72;                      // 64 elems + 8 pad
    constexpr int A_BYTES = MT * RS * 2;
    constexpr int B_BYTES = 64 * RS * 2;
    constexpr int OFF_AL = A_BYTES;
    constexpr int OFF_BH = 2 * A_BYTES;
    constexpr int SS = 2 * A_BYTES + 2 * B_BYTES;

    uint32_t sb = smem_u32(smem);
    const int tid = threadIdx.x;
    const int m0 = blockIdx.y * MT, n0 = blockIdx.x * 64;

    if (flags && blockIdx.x == 0 && blockIdx.y == 0 && tid < NBH * NCH)
        flags[tid] = 0;

    const int lane = tid & 31, wid = tid >> 5;
    const int wm = (wid >> 1) * (MT / 4);       // 128: 0,32,64,96  64: 0,16,32,48
    const int wn = (wid & 1) * 32;
    const int lr = lane & 15, lc = lane >> 4;

    auto load_stage = [&](int buf, int k0) {
        uint32_t st = sb + buf * SS;
#pragma unroll
        for (int u = tid; u < MT * 8; u += THREADS) {
            int r = u >> 3, c = u & 7;
            uint32_t d = st + (uint32_t)(r * RS + c * 8) * 2;
            cp_async16(d,          Ah + (size_t)(m0 + r) * K + k0 + c * 8);
            cp_async16(d + OFF_AL, Al + (size_t)(m0 + r) * K + k0 + c * 8);
        }
#pragma unroll
        for (int u = tid; u < 512; u += THREADS) {
            int r = u >> 3, c = u & 7;
            uint32_t d = st + OFF_BH + (uint32_t)(r * RS + c * 8) * 2;
            cp_async16(d,           Bh + (size_t)(n0 + r) * K + k0 + c * 8);
            cp_async16(d + B_BYTES, Bl + (size_t)(n0 + r) * K + k0 + c * 8);
        }
    };

    const int NST = K >> 6;                     // BK = 64
    load_stage(0, 0);
    cp_commit();

    constexpr int MW = (MT == 128) ? 2 : 1;     // 16-row m-tiles per warp
    float acc[MW][4][4] = {};

    for (int s = 0; s < NST; s++) {
        asm volatile("cp.async.wait_group 0;" ::: "memory");
        __syncthreads();
        if (s + 1 < NST) { load_stage((s + 1) & 1, (s + 1) << 6); cp_commit(); }

        uint32_t st = sb + (s & 1) * SS;
#pragma unroll
        for (int kk = 0; kk < 4; kk++) {
            uint32_t ah[MW][4], al[MW][4], bh[2][4], bl[2][4];
#pragma unroll
            for (int mt = 0; mt < MW; mt++) {
                uint32_t ad = st + (uint32_t)((wm + mt * 16 + lr) * RS + kk * 16 + lc * 8) * 2;
                ldsm_x4(ah[mt], ad);
                ldsm_x4(al[mt], ad + OFF_AL);
            }
#pragma unroll
            for (int np = 0; np < 2; np++) {
                uint32_t bd = st + OFF_BH + (uint32_t)((wn + np * 16 + lr) * RS + kk * 16 + lc * 8) * 2;
                ldsm_x4(bh[np], bd);
                ldsm_x4(bl[np], bd + B_BYTES);
            }
#pragma unroll
            for (int mt = 0; mt < MW; mt++)
#pragma unroll
                for (int nt = 0; nt < 4; nt++) {
                    uint32_t bhp[2] = { bh[nt >> 1][nt & 1], bh[nt >> 1][2 + (nt & 1)] };
                    uint32_t blp[2] = { bl[nt >> 1][nt & 1], bl[nt >> 1][2 + (nt & 1)] };
                    mma_bf16(acc[mt][nt], ah[mt], bhp);
                    mma_bf16(acc[mt][nt], ah[mt], blp);
                    mma_bf16(acc[mt][nt], al[mt], bhp);
                }
        }
    }

    const int tr = lane >> 2;
    const int tc = (lane & 3) * 2;
#pragma unroll
    for (int mt = 0; mt < MW; mt++) {
#pragma unroll
        for (int nt = 0; nt < 4; nt++) {
            int col = n0 + wn + nt * 8 + tc;
            float b0 = bias[col], b1 = bias[col + 1];
#pragma unroll
            for (int half = 0; half < 2; half++) {
                int row = m0 + wm + mt * 16 + tr + half * 8;
                float v0 = acc[mt][nt][half * 2]     + b0;
                float v1 = acc[mt][nt][half * 2 + 1] + b1;
                if (EPI == 1) {
                    v0 = gelu_exact(v0);
                    v1 = gelu_exact(v1);
                    __nv_bfloat16 h0 = __float2bfloat16(v0);
                    __nv_bfloat16 h1 = __float2bfloat16(v1);
                    __nv_bfloat162 hp; hp.x = h0; hp.y = h1;
                    __nv_bfloat162 lp;
                    lp.x = __float2bfloat16(v0 - __bfloat162float(h0));
                    lp.y = __float2bfloat16(v1 - __bfloat162float(h1));
                    *(__nv_bfloat162*)&Ch[(size_t)row * N + col] = hp;
                    *(__nv_bfloat162*)&Cl[(size_t)row * N + col] = lp;
                } else {
                    if (EPI == 2) {
                        float2 rv = *(const float2*)&Res[(size_t)row * N + col];
                        v0 += rv.x; v1 += rv.y;
                    }
                    float2 ov; ov.x = v0; ov.y = v1;
                    *(float2*)&Cf[(size_t)row * N + col] = ov;
                }
            }
        }
    }
}

// ---------------- fused attention: chunk sums + lookback prefix + output ----
__global__ __launch_bounds__(256) void attn_fused_kernel(
    const float* __restrict__ qkv, float* __restrict__ S,
    float* __restrict__ ks, int* __restrict__ flags,
    __nv_bfloat16* __restrict__ oh, __nv_bfloat16* __restrict__ ol)
{
    extern __shared__ float sm[];
    float* Ks   = sm;               // 64 x PS  phi(k)
    float* Vs   = sm + 64  * PS;    // 64 x PS  v
    float* Qs   = sm + 128 * PS;    // 64 x PS  phi(q)
    float* Psh  = sm + 192 * PS;    // 64 x PS  exclusive prefix P[d][e]
    float* As   = sm + 256 * PS;    // 64 x PS  masked QK^T
    float* dens = sm + 320 * PS;    // 64
    float* kps  = dens + 64;        // 64

    const int blk = blockIdx.x;
    const int bh = blk / NCH, c = blk % NCH;
    const int b = bh / HH, h = bh % HH;
    const int tid = threadIdx.x;
    const int d0 = (tid >> 4) * 4, e0 = (tid & 15) * 4;

    // 1. load K (phi) and V
#pragma unroll
    for (int i = tid; i < 4096; i += 256) {
        int t = i >> 6, d = i & 63;
        int row = b * LL + c * CHUNK + t;
        float kv = qkv[row * 768 + 256 + h * 64 + d];
        Ks[t * PS + d] = fmaxf(kv, 0.f) + 1e-6f;
        Vs[t * PS + d] = qkv[row * 768 + 512 + h * 64 + d];
    }
    __syncthreads();

    // 2. own chunk sums -> global, publish flag (release)
    {
        float sc[4][4] = {};
#pragma unroll 4
        for (int t = 0; t < 64; t++) {
            float kd[4], ve[4];
            *(float4*)kd = *(const float4*)&Ks[t * PS + d0];
            *(float4*)ve = *(const float4*)&Vs[t * PS + e0];
#pragma unroll
            for (int i = 0; i < 4; i++)
#pragma unroll
                for (int j = 0; j < 4; j++)
                    sc[i][j] += kd[i] * ve[j];
        }
        float* So = S + (size_t)blk * 4096;
#pragma unroll
        for (int i = 0; i < 4; i++)
            *(float4*)&So[(d0 + i) * 64 + e0] =
                make_float4(sc[i][0], sc[i][1], sc[i][2], sc[i][3]);
        if (tid < 64) {
            float s = 0.f;
#pragma unroll 8
            for (int t = 0; t < 64; t++) s += Ks[t * PS + tid];
            ks[blk * 64 + tid] = s;
        }
    }
    __syncthreads();
    if (tid == 0) { __threadfence(); atomicExch(&flags[blk], 1); }

    // 3. load Q (phi)
#pragma unroll
    for (int i = tid; i < 4096; i += 256) {
        int t = i >> 6, d = i & 63;
        int row = b * LL + c * CHUNK + t;
        float qv = qkv[row * 768 + h * 64 + d];
        Qs[t * PS + d] = fmaxf(qv, 0.f) + 1e-6f;
    }

    // 4. wait for predecessor chunks (acquire)
    if (tid < c) {
        while (atomicAdd(&flags[bh * NCH + tid], 0) == 0) { __nanosleep(60); }
        __threadfence();
    }
    __syncthreads();

    // 5. exclusive prefix
    {
        float pr[4][4] = {};
        for (int cc = 0; cc < c; cc++) {
            const float* Sp = S + (size_t)(bh * NCH + cc) * 4096;
#pragma unroll
            for (int i = 0; i < 4; i++) {
                float4 v = *(const float4*)&Sp[(d0 + i) * 64 + e0];
                pr[i][0] += v.x; pr[i][1] += v.y; pr[i][2] += v.z; pr[i][3] += v.w;
            }
        }
#pragma unroll
        for (int i = 0; i < 4; i++)
            *(float4*)&Psh[(d0 + i) * PS + e0] =
                make_float4(pr[i][0], pr[i][1], pr[i][2], pr[i][3]);
        if (tid < 64) {
            float s = 0.f;
            for (int cc = 0; cc < c; cc++) s += ks[(bh * NCH + cc) * 64 + tid];
            kps[tid] = s;
        }
    }
    __syncthreads();

    const int i0 = d0, j0 = e0;
    float acc[4][4] = {};

    // 6. acc = Q @ P ; den = q . kps
#pragma unroll 2
    for (int d = 0; d < 64; d += 4) {
        float qv[4][4], pv[4][4];
#pragma unroll
        for (int i = 0; i < 4; i++)
            *(float4*)qv[i] = *(const float4*)&Qs[(i0 + i) * PS + d];
#pragma unroll
        for (int dd = 0; dd < 4; dd++)
            *(float4*)pv[dd] = *(const float4*)&Psh[(d + dd) * PS + j0];
#pragma unroll
        for (int i = 0; i < 4; i++)
#pragma unroll
            for (int j = 0; j < 4; j++)
#pragma unroll
                for (int dd = 0; dd < 4; dd++)
                    acc[i][j] += qv[i][dd] * pv[dd][j];
    }
    if (tid < 64) {
        float s = 0.f;
#pragma unroll
        for (int d = 0; d < 64; d += 4) {
            float4 q4 = *(const float4*)&Qs[tid * PS + d];
            float4 k4 = *(const float4*)&kps[d];
            s += q4.x * k4.x + q4.y * k4.y + q4.z * k4.z + q4.w * k4.w;
        }
        dens[tid] = s;
    }

    // 7. A = tril(Q K^T)
    {
        float av[4][4] = {};
#pragma unroll 2
        for (int d = 0; d < 64; d += 4) {
            float qv[4][4], kv[4][4];
#pragma unroll
            for (int i = 0; i < 4; i++)
                *(float4*)qv[i] = *(const float4*)&Qs[(i0 + i) * PS + d];
#pragma unroll
            for (int j = 0; j < 4; j++)
                *(float4*)kv[j] = *(const float4*)&Ks[(j0 + j) * PS + d];
#pragma unroll
            for (int i = 0; i < 4; i++)
#pragma unroll
                for (int j = 0; j < 4; j++)
#pragma unroll
                    for (int dd = 0; dd < 4; dd++)
                        av[i][j] += qv[i][dd] * kv[j][dd];
        }
#pragma unroll
        for (int i = 0; i < 4; i++) {
            float4 o;
            o.x = (j0 + 0 <= i0 + i) ? av[i][0] : 0.f;
            o.y = (j0 + 1 <= i0 + i) ? av[i][1] : 0.f;
            o.z = (j0 + 2 <= i0 + i) ? av[i][2] : 0.f;
            o.w = (j0 + 3 <= i0 + i) ? av[i][3] : 0.f;
            *(float4*)&As[(i0 + i) * PS + j0] = o;
        }
    }
    __syncthreads();

    // 8. den += rowsum(A)
    if (tid < 64) {
        float rs = 0.f;
#pragma unroll
        for (int j = 0; j < 64; j += 4) {
            float4 a4 = *(const float4*)&As[tid * PS + j];
            rs += a4.x + a4.y + a4.z + a4.w;
        }
        dens[tid] += rs;
    }
    __syncthreads();

    // 9. acc += A @ V; write bf16 hi/lo
#pragma unroll 2
    for (int j = 0; j < 64; j += 4) {
        float av[4][4], vv[4][4];
#pragma unroll
        for (int i = 0; i < 4; i++)
            *(float4*)av[i] = *(const float4*)&As[(i0 + i) * PS + j];
#pragma unroll
        for (int m = 0; m < 4; m++)
            *(float4*)vv[m] = *(const float4*)&Vs[(j + m) * PS + j0];
#pragma unroll
        for (int i = 0; i < 4; i++)
#pragma unroll
            for (int jj = 0; jj < 4; jj++)
#pragma unroll
                for (int m = 0; m < 4; m++)
                    acc[i][jj] += av[i][m] * vv[m][jj];
    }

#pragma unroll
    for (int i = 0; i < 4; i++) {
        float dn = fmaxf(dens[i0 + i], 1e-6f);
        int row = b * LL + c * CHUNK + i0 + i;
        float inv = 1.0f / dn;
        size_t idx = (size_t)row * EE + h * 64 + j0;
        __nv_bfloat162 hp0, hp1, lp0, lp1;
        float v0 = acc[i][0] * inv, v1 = acc[i][1] * inv;
        float v2 = acc[i][2] * inv, v3 = acc[i][3] * inv;
        __nv_bfloat16 h0 = __float2bfloat16(v0), h1 = __float2bfloat16(v1);
        __nv_bfloat16 h2 = __float2bfloat16(v2), h3 = __float2bfloat16(v3);
        hp0.x = h0; hp0.y = h1; hp1.x = h2; hp1.y = h3;
        lp0.x = __float2bfloat16(v0 - __bfloat162float(h0));
        lp0.y = __float2bfloat16(v1 - __bfloat162float(h1));
        lp1.x = __float2bfloat16(v2 - __bfloat162float(h2));
        lp1.y = __float2bfloat16(v3 - __bfloat162float(h3));
        uint2 hh, ll;
        hh.x = *(uint32_t*)&hp0; hh.y = *(uint32_t*)&hp1;
        ll.x = *(uint32_t*)&lp0; ll.y = *(uint32_t*)&lp1;
        *(uint2*)&oh[idx] = hh;
        *(uint2*)&ol[idx] = ll;
    }
}

// ---------------- final LN + pred fused -------------------------------------
__global__ __launch_bounds__(256) void predln_kernel(
    const float* __restrict__ x, const float* __restrict__ g,
    const float* __restrict__ bta,
    const float* __restrict__ pred_w, const float* __restrict__ pred_b,
    float* __restrict__ out)
{
    int bk = blockIdx.x;
    int b = bk / KSTEP, k = bk % KSTEP;
    int row = b * LL + 3 * k + 1;
    int e = threadIdx.x;
    __shared__ float red[8];
    __shared__ float ys[EE];

    float v = x[(size_t)row * EE + e];
    float s = v;
#pragma unroll
    for (int o = 16; o; o >>= 1) s += __shfl_xor_sync(0xffffffffu, s, o);
    if ((e & 31) == 0) red[e >> 5] = s;
    __syncthreads();
    if (e < 8) {
        float t = red[e];
#pragma unroll
        for (int o = 4; o; o >>= 1) t += __shfl_xor_sync(0xffu, t, o);
        if (e == 0) red[0] = t;
    }
    __syncthreads();
    float mean = red[0] * (1.0f / EE);
    __syncthreads();
    float d = v - mean;
    float s2 = d * d;
#pragma unroll
    for (int o = 16; o; o >>= 1) s2 += __shfl_xor_sync(0xffffffffu, s2, o);
    if ((e & 31) == 0) red[e >> 5] = s2;
    __syncthreads();
    if (e < 8) {
        float t = red[e];
#pragma unroll
        for (int o = 4; o; o >>= 1) t += __shfl_xor_sync(0xffu, t, o);
        if (e == 0) red[0] = t;
    }
    __syncthreads();
    float var = red[0] * (1.0f / EE);
    float r = rsqrtf(var + 1e-5f);
    ys[e] = d * r * g[e] + bta[e];
    __syncthreads();

    int w = e >> 5, lane = e & 31;
    if (w < NACT) {
        float sum = 0.f;
        for (int i = lane; i < EE; i += 32) sum += ys[i] * pred_w[i * NACT + w];
#pragma unroll
        for (int o = 16; o; o >>= 1) sum += __shfl_xor_sync(0xffffffffu, sum, o);
        if (lane == 0) out[bk * NACT + w] = sum + pred_b[w];
    }
}

// ---------------- launch ----------------------------------------------------
extern "C" void kernel_launch(void* const* d_in, const int* in_sizes, int n_in,
                              void* d_out, int out_size)
{
    const float* rtg      = (const float*)d_in[0];
    const float* state    = (const float*)d_in[1];
    const float* action   = (const float*)d_in[2];
    const float* rtg_w    = (const float*)d_in[3];
    const float* rtg_b    = (const float*)d_in[4];
    const float* state_w  = (const float*)d_in[5];
    const float* state_b  = (const float*)d_in[6];
    const float* action_w = (const float*)d_in[7];
    const float* action_b = (const float*)d_in[8];
    const float* pos_emb  = (const float*)d_in[9];
    const float* norm1_g  = (const float*)d_in[10];
    const float* norm1_b  = (const float*)d_in[11];
    const float* qkv_w    = (const float*)d_in[12];
    const float* qkv_b    = (const float*)d_in[13];
    const float* out_w    = (const float*)d_in[14];
    const float* out_b    = (const float*)d_in[15];
    const float* norm2_g  = (const float*)d_in[16];
    const float* norm2_b  = (const float*)d_in[17];
    const float* ffn1_w   = (const float*)d_in[18];
    const float* ffn1_b   = (const float*)d_in[19];
    const float* ffn2_w   = (const float*)d_in[20];
    const float* ffn2_b   = (const float*)d_in[21];
    const float* normf_g  = (const float*)d_in[22];
    const float* normf_b  = (const float*)d_in[23];
    const float* pred_w   = (const float*)d_in[24];
    const float* pred_b   = (const float*)d_in[25];

    float *x, *xn, *qkv, *S, *ks;
    int* flags;
    __nv_bfloat16 *xh, *xl, *oh, *ol, *ffh, *ffl, *wh, *wl;
    cudaGetSymbolAddress((void**)&x,     g_x);
    cudaGetSymbolAddress((void**)&xn,    g_xn);
    cudaGetSymbolAddress((void**)&qkv,   g_qkv);
    cudaGetSymbolAddress((void**)&S,     g_S);
    cudaGetSymbolAddress((void**)&ks,    g_ks);
    cudaGetSymbolAddress((void**)&flags, g_flag);
    cudaGetSymbolAddress((void**)&xh,    g_xh);
    cudaGetSymbolAddress((void**)&xl,    g_xl);
    cudaGetSymbolAddress((void**)&oh,    g_oh);
    cudaGetSymbolAddress((void**)&ol,    g_ol);
    cudaGetSymbolAddress((void**)&ffh,   g_ffh);
    cudaGetSymbolAddress((void**)&ffl,   g_ffl);
    cudaGetSymbolAddress((void**)&wh,    g_wh);
    cudaGetSymbolAddress((void**)&wl,    g_wl);

    const int SMEM_ATT  = (320 * PS + 128) * sizeof(float);        // 87552
    const int SMEM_G128 = 2 * (2 * 128 * 72 * 2 + 2 * 64 * 72 * 2); // 110592
    const int SMEM_G64  = 2 * (4 * 64 * 72 * 2);                    // 73728
    cudaFuncSetAttribute(attn_fused_kernel,
                         cudaFuncAttributeMaxDynamicSharedMemorySize, SMEM_ATT);
    cudaFuncSetAttribute((const void*)gemm_mma_kernel<128, 0>,
                         cudaFuncAttributeMaxDynamicSharedMemorySize, SMEM_G128);
    cudaFuncSetAttribute((const void*)gemm_mma_kernel<128, 1>,
                         cudaFuncAttributeMaxDynamicSharedMemorySize, SMEM_G128);
    cudaFuncSetAttribute((const void*)gemm_mma_kernel<64, 2>,
                         cudaFuncAttributeMaxDynamicSharedMemorySize, SMEM_G64);

    prep_kernel<<<dim3(32, 32, 11), 256>>>(
        qkv_w, out_w, ffn1_w, ffn2_w, wh, wl,
        rtg, state, action, rtg_w, rtg_b, state_w, state_b,
        action_w, action_b, pos_emb, norm1_g, norm1_b, x, xh, xl);

    for (int layer = 0; layer < NLAYER; layer++) {
        const float* n2g = norm2_g + layer * EE;
        const float* n2b = norm2_b + layer * EE;
        const float* qb  = qkv_b  + layer * 3 * EE;
        const float* ob  = out_b  + layer * EE;
        const float* f1b = ffn1_b + layer * FFD;
        const float* f2b = ffn2_b + layer * EE;
        size_t qoff  = (size_t)layer * 196608;
        size_t ooff  = 393216  + (size_t)layer * 65536;
        size_t f1off = 524288  + (size_t)layer * 262144;
        size_t f2off = 1048576 + (size_t)layer * 262144;
        int* lflags = flags + layer * NBH * NCH;

        if (layer > 0) {
            ln4_kernel<<<MTOK / 4, 256>>>(x, norm1_g + layer * EE, norm1_b + layer * EE,
                                          xn, xh, xl);
        }

        gemm_mma_kernel<128, 0><<<dim3(12, 24), 256, SMEM_G128>>>(
            xh, xl, wh + qoff, wl + qoff, qb, nullptr, qkv, nullptr, nullptr,
            768, 256, lflags);

        attn_fused_kernel<<<NBH * NCH, 256, SMEM_ATT>>>(qkv, S, ks, lflags, oh, ol);

        gemm_mma_kernel<64, 2><<<dim3(4, 48), 256, SMEM_G64>>>(
            oh, ol, wh + ooff, wl + ooff, ob, x, x, nullptr, nullptr,
            256, 256, nullptr);

        ln4_kernel<<<MTOK / 4, 256>>>(x, n2g, n2b, xn, xh, xl);

        gemm_mma_kernel<128, 1><<<dim3(16, 24), 256, SMEM_G128>>>(
            xh, xl, wh + f1off, wl + f1off, f1b, nullptr, nullptr, ffh, ffl,
            1024, 256, nullptr);

        gemm_mma_kernel<64, 2><<<dim3(4, 48), 256, SMEM_G64>>>(
            ffh, ffl, wh + f2off, wl + f2off, f2b, x, x, nullptr, nullptr,
            256, 1024, nullptr);
    }

    predln_kernel<<<BB * KSTEP, 256>>>(x, normf_g, normf_b, pred_w, pred_b,
                                       (float*)d_out);
}

// round 15
// speedup vs baseline: 1.3897x; 1.0664x over previous
#include <cuda_runtime.h>
#include <cuda_bf16.h>
#include <math.h>
#include <stdint.h>

#define BB     2
#define KSTEP  512
#define SDIM   60
#define NACT   5
#define EE     256
#define HH     4
#define DD     64
#define FFD    1024
#define NLAYER 2
#define LL     1536          // 3*KSTEP
#define MTOK   3072          // BB*LL
#define CHUNK  64
#define NCH    24            // LL/CHUNK
#define NBH    8             // BB*HH

#define WTOT   1572864       // total split-weight elements (bf16)
#define PS     68            // padded smem row stride (floats) for attention

// ---------------- scratch (device globals; no allocation) ----------------
__device__ float g_x  [MTOK * EE];
__device__ float g_xn [MTOK * EE];
__device__ float g_qkv[MTOK * 3 * EE];
__device__ float g_S  [NBH * NCH * DD * DD];
__device__ float g_ks [NBH * NCH * DD];
__device__ int   g_flag[NLAYER * NBH * NCH];
__device__ __nv_bfloat16 g_xh [MTOK * EE];
__device__ __nv_bfloat16 g_xl [MTOK * EE];
__device__ __nv_bfloat16 g_oh [MTOK * EE];
__device__ __nv_bfloat16 g_ol [MTOK * EE];
__device__ __nv_bfloat16 g_ffh[MTOK * FFD];
__device__ __nv_bfloat16 g_ffl[MTOK * FFD];
__device__ __nv_bfloat16 g_wh [WTOT];
__device__ __nv_bfloat16 g_wl [WTOT];

// ---------------- helpers ----------------------------------------------------
__device__ __forceinline__ uint32_t smem_u32(const void* p) {
    uint32_t a;
    asm("{ .reg .u64 t; cvta.to.shared.u64 t, %1; cvt.u32.u64 %0, t; }" : "=r"(a) : "l"(p));
    return a;
}
__device__ __forceinline__ void cp_async16(uint32_t dst, const void* src) {
    asm volatile("cp.async.cg.shared.global [%0], [%1], 16;" :: "r"(dst), "l"(src) : "memory");
}
__device__ __forceinline__ void cp_commit() { asm volatile("cp.async.commit_group;" ::: "memory"); }

__device__ __forceinline__ void ldsm_x4(uint32_t* r, uint32_t addr) {
    asm volatile("ldmatrix.sync.aligned.m8n8.x4.shared.b16 {%0,%1,%2,%3}, [%4];"
                 : "=r"(r[0]), "=r"(r[1]), "=r"(r[2]), "=r"(r[3]) : "r"(addr));
}
__device__ __forceinline__ void mma_bf16(float* c, const uint32_t* a, const uint32_t* b) {
    asm volatile(
        "mma.sync.aligned.m16n8k16.row.col.f32.bf16.bf16.f32 "
        "{%0,%1,%2,%3}, {%4,%5,%6,%7}, {%8,%9}, {%0,%1,%2,%3};"
        : "+f"(c[0]), "+f"(c[1]), "+f"(c[2]), "+f"(c[3])
        : "r"(a[0]), "r"(a[1]), "r"(a[2]), "r"(a[3]), "r"(b[0]), "r"(b[1]));
}

__device__ __forceinline__ float gelu_exact(float x) {
    return 0.5f * x * (1.0f + erff(x * 0.70710678118654752f));
}

// ---------------- prep: weight split (z<8) + embed+LN1 (z>=8) ---------------
__global__ __launch_bounds__(256) void prep_kernel(
    const float* __restrict__ qkv_w, const float* __restrict__ out_w,
    const float* __restrict__ f1w, const float* __restrict__ f2w,
    __nv_bfloat16* __restrict__ Wh, __nv_bfloat16* __restrict__ Wl,
    const float* __restrict__ rtg, const float* __restrict__ state,
    const float* __restrict__ action,
    const float* __restrict__ rtg_w, const float* __restrict__ rtg_b,
    const float* __restrict__ state_w, const float* __restrict__ state_b,
    const float* __restrict__ action_w, const float* __restrict__ action_b,
    const float* __restrict__ pos,
    const float* __restrict__ g, const float* __restrict__ bta,
    float* __restrict__ x,
    __nv_bfloat16* __restrict__ yh, __nv_bfloat16* __restrict__ yl)
{
    int z = blockIdx.z;
    int tid = threadIdx.x;
    if (z < 8) {
        const float* src; int Kd, Nd; size_t doff;
        switch (z) {
            case 0: src = qkv_w;          Kd = 256;  Nd = 768;  doff = 0;       break;
            case 1: src = qkv_w + 196608; Kd = 256;  Nd = 768;  doff = 196608;  break;
            case 2: src = out_w;          Kd = 256;  Nd = 256;  doff = 393216;  break;
            case 3: src = out_w + 65536;  Kd = 256;  Nd = 256;  doff = 458752;  break;
            case 4: src = f1w;            Kd = 256;  Nd = 1024; doff = 524288;  break;
            case 5: src = f1w + 262144;   Kd = 256;  Nd = 1024; doff = 786432;  break;
            case 6: src = f2w;            Kd = 1024; Nd = 256;  doff = 1048576; break;
            default:src = f2w + 262144;   Kd = 1024; Nd = 256;  doff = 1310720; break;
        }
        int nt = blockIdx.x * 32, kt = blockIdx.y * 32;
        if (nt >= Nd || kt >= Kd) return;
        __shared__ float t[32][33];
        int tx = tid & 31, ty = tid >> 5;
#pragma unroll
        for (int i = 0; i < 4; i++) {
            int r = kt + ty + i * 8;
            t[ty + i * 8][tx] = src[(size_t)r * Nd + nt + tx];
        }
        __syncthreads();
#pragma unroll
        for (int i = 0; i < 4; i++) {
            int n = nt + ty + i * 8;
            int k = kt + tx;
            float v = t[tx][ty + i * 8];
            __nv_bfloat16 h = __float2bfloat16(v);
            Wh[doff + (size_t)n * Kd + k] = h;
            Wl[doff + (size_t)n * Kd + k] = __float2bfloat16(v - __bfloat162float(h));
        }
        return;
    }

    int tok = blockIdx.x + blockIdx.y * 32 + (z - 8) * 1024;
    if (tok >= MTOK) return;
    int e   = tid;
    int b   = tok / LL;
    int l   = tok % LL;
    int k   = l / 3;
    int typ = l % 3;
    float acc = pos[k * EE + e];
    if (typ == 0) {
        acc += rtg[b * KSTEP + k] * rtg_w[e] + rtg_b[e];
    } else if (typ == 1) {
        const float* s = state + (b * KSTEP + k) * SDIM;
        float sum = 0.f;
        for (int i = 0; i < SDIM; i++) sum += s[i] * state_w[i * EE + e];
        acc += sum + state_b[e];
    } else {
        const float* a = action + (b * KSTEP + k) * NACT;
        float sum = 0.f;
#pragma unroll
        for (int i = 0; i < NACT; i++) sum += a[i] * action_w[i * EE + e];
        acc += sum + action_b[e];
    }
    x[tok * EE + e] = acc;

    __shared__ float red[8];
    float s = acc;
#pragma unroll
    for (int o = 16; o; o >>= 1) s += __shfl_xor_sync(0xffffffffu, s, o);
    if ((e & 31) == 0) red[e >> 5] = s;
    __syncthreads();
    if (e < 8) {
        float t2 = red[e];
#pragma unroll
        for (int o = 4; o; o >>= 1) t2 += __shfl_xor_sync(0xffu, t2, o);
        if (e == 0) red[0] = t2;
    }
    __syncthreads();
    float mean = red[0] * (1.0f / EE);
    __syncthreads();
    float d  = acc - mean;
    float s2 = d * d;
#pragma unroll
    for (int o = 16; o; o >>= 1) s2 += __shfl_xor_sync(0xffffffffu, s2, o);
    if ((e & 31) == 0) red[e >> 5] = s2;
    __syncthreads();
    if (e < 8) {
        float t2 = red[e];
#pragma unroll
        for (int o = 4; o; o >>= 1) t2 += __shfl_xor_sync(0xffu, t2, o);
        if (e == 0) red[0] = t2;
    }
    __syncthreads();
    float var = red[0] * (1.0f / EE);
    float r = rsqrtf(var + 1e-5f);
    float yv = d * r * g[e] + bta[e];
    __nv_bfloat16 h = __float2bfloat16(yv);
    yh[tok * EE + e] = h;
    yl[tok * EE + e] = __float2bfloat16(yv - __bfloat162float(h));
}

// ---------------- LayerNorm: 4 rows/block, float4 ---------------------------
__global__ __launch_bounds__(256) void ln4_kernel(
    const float* __restrict__ x, const float* __restrict__ g,
    const float* __restrict__ bta, float* __restrict__ y,
    __nv_bfloat16* __restrict__ yh, __nv_bfloat16* __restrict__ yl)
{
    __shared__ float red[16];
    int tid = threadIdx.x;
    int r   = tid >> 6;
    int l64 = tid & 63;
    int w   = tid >> 5;
    int lane = tid & 31;
    int row = blockIdx.x * 4 + r;
    size_t base = (size_t)row * EE + l64 * 4;

    float4 v = *(const float4*)&x[base];
    float s = v.x + v.y + v.z + v.w;
#pragma unroll
    for (int o = 16; o; o >>= 1) s += __shfl_xor_sync(0xffffffffu, s, o);
    if (lane == 0) red[w] = s;
    __syncthreads();
    float mean = (red[2 * r] + red[2 * r + 1]) * (1.0f / EE);

    float4 d;
    d.x = v.x - mean; d.y = v.y - mean; d.z = v.z - mean; d.w = v.w - mean;
    float s2 = d.x * d.x + d.y * d.y + d.z * d.z + d.w * d.w;
#pragma unroll
    for (int o = 16; o; o >>= 1) s2 += __shfl_xor_sync(0xffffffffu, s2, o);
    if (lane == 0) red[8 + w] = s2;
    __syncthreads();
    float var = (red[8 + 2 * r] + red[8 + 2 * r + 1]) * (1.0f / EE);
    float rs = rsqrtf(var + 1e-5f);

    float4 gv = *(const float4*)&g[l64 * 4];
    float4 bv = *(const float4*)&bta[l64 * 4];
    float4 o;
    o.x = d.x * rs * gv.x + bv.x;
    o.y = d.y * rs * gv.y + bv.y;
    o.z = d.z * rs * gv.z + bv.z;
    o.w = d.w * rs * gv.w + bv.w;
    *(float4*)&y[base] = o;

    __nv_bfloat16 h0 = __float2bfloat16(o.x), h1 = __float2bfloat16(o.y);
    __nv_bfloat16 h2 = __float2bfloat16(o.z), h3 = __float2bfloat16(o.w);
    __nv_bfloat162 hp0; hp0.x = h0; hp0.y = h1;
    __nv_bfloat162 hp1; hp1.x = h2; hp1.y = h3;
    __nv_bfloat162 lp0, lp1;
    lp0.x = __float2bfloat16(o.x - __bfloat162float(h0));
    lp0.y = __float2bfloat16(o.y - __bfloat162float(h1));
    lp1.x = __float2bfloat16(o.z - __bfloat162float(h2));
    lp1.y = __float2bfloat16(o.w - __bfloat162float(h3));
    uint2 hh, ll;
    hh.x = *(uint32_t*)&hp0; hh.y = *(uint32_t*)&hp1;
    ll.x = *(uint32_t*)&lp0; ll.y = *(uint32_t*)&lp1;
    *(uint2*)&yh[base] = hh;
    *(uint2*)&yl[base] = ll;
}

// ---------------- HMMA GEMM: MTx64 tile, BK=64, 2-stage, bf16-split ---------
// MT=128: 4m x 2n warps (32x32/warp). MT=64: 4m x 2n (16x32). MT=32: 2m x 4n (16x16).
// Also zeroes `flags` (192 ints) from block (0,0) when non-null.
template <int MT, int EPI>
__global__ __launch_bounds__(256) void gemm_mma_kernel(
    const __nv_bfloat16* __restrict__ Ah, const __nv_bfloat16* __restrict__ Al,
    const __nv_bfloat16* __restrict__ Bh, const __nv_bfloat16* __restrict__ Bl,
    const float* __restrict__ bias, const float* Res,
    float* Cf, __nv_bfloat16* Ch, __nv_bfloat16* Cl,
    int N, int K, int* flags)
{
    extern __shared__ char smem[];
    constexpr int THREADS = 256;
    constexpr int RS = 72;                      // 64 elems + 8 pad
    constexpr int A_BYTES = MT * RS * 2;
    constexpr int B_BYTES = 64 * RS * 2;
    constexpr int OFF_AL = A_BYTES;
    constexpr int OFF_BH = 2 * A_BYTES;
    constexpr int SS = 2 * A_BYTES + 2 * B_BYTES;

    constexpr int WN_WARPS = (MT == 32) ? 4 : 2;    // warps along n
    constexpr int WM_WARPS = 8 / WN_WARPS;          // warps along m
    constexpr int WM_ROWS  = MT / WM_WARPS;         // rows per warp (32/16/16)
    constexpr int MW       = WM_ROWS / 16;          // 16-row m-tiles per warp
    constexpr int WN_COLS  = 64 / WN_WARPS;         // cols per warp (32/32/16)
    constexpr int NB       = WN_COLS / 16;          // 16-col b tiles (2/2/1)
    constexpr int NT_CNT   = WN_COLS / 8;           // 8-col acc tiles (4/4/2)

    uint32_t sb = smem_u32(smem);
    const int tid = threadIdx.x;
    const int m0 = blockIdx.y * MT, n0 = blockIdx.x * 64;

    if (flags && blockIdx.x == 0 && blockIdx.y == 0 && tid < NBH * NCH)
        flags[tid] = 0;

    const int lane = tid & 31, wid = tid >> 5;
    const int wm = (wid / WN_WARPS) * WM_ROWS;
    const int wn = (wid % WN_WARPS) * WN_COLS;
    const int lr = lane & 15, lc = lane >> 4;

    auto load_stage = [&](int buf, int k0) {
        uint32_t st = sb + buf * SS;
#pragma unroll
        for (int u = tid; u < MT * 8; u += THREADS) {
            int r = u >> 3, c = u & 7;
            uint32_t d = st + (uint32_t)(r * RS + c * 8) * 2;
            cp_async16(d,          Ah + (size_t)(m0 + r) * K + k0 + c * 8);
            cp_async16(d + OFF_AL, Al + (size_t)(m0 + r) * K + k0 + c * 8);
        }
#pragma unroll
        for (int u = tid; u < 512; u += THREADS) {
            int r = u >> 3, c = u & 7;
            uint32_t d = st + OFF_BH + (uint32_t)(r * RS + c * 8) * 2;
            cp_async16(d,           Bh + (size_t)(n0 + r) * K + k0 + c * 8);
            cp_async16(d + B_BYTES, Bl + (size_t)(n0 + r) * K + k0 + c * 8);
        }
    };

    const int NST = K >> 6;                     // BK = 64
    load_stage(0, 0);
    cp_commit();

    float acc[MW][NT_CNT][4] = {};

    for (int s = 0; s < NST; s++) {
        asm volatile("cp.async.wait_group 0;" ::: "memory");
        __syncthreads();
        if (s + 1 < NST) { load_stage((s + 1) & 1, (s + 1) << 6); cp_commit(); }

        uint32_t st = sb + (s & 1) * SS;
#pragma unroll
        for (int kk = 0; kk < 4; kk++) {
            uint32_t ah[MW][4], al[MW][4], bh[NB][4], bl[NB][4];
#pragma unroll
            for (int mt = 0; mt < MW; mt++) {
                uint32_t ad = st + (uint32_t)((wm + mt * 16 + lr) * RS + kk * 16 + lc * 8) * 2;
                ldsm_x4(ah[mt], ad);
                ldsm_x4(al[mt], ad + OFF_AL);
            }
#pragma unroll
            for (int np = 0; np < NB; np++) {
                uint32_t bd = st + OFF_BH + (uint32_t)((wn + np * 16 + lr) * RS + kk * 16 + lc * 8) * 2;
                ldsm_x4(bh[np], bd);
                ldsm_x4(bl[np], bd + B_BYTES);
            }
#pragma unroll
            for (int mt = 0; mt < MW; mt++)
#pragma unroll
                for (int nt = 0; nt < NT_CNT; nt++) {
                    uint32_t bhp[2] = { bh[nt >> 1][nt & 1], bh[nt >> 1][2 + (nt & 1)] };
                    uint32_t blp[2] = { bl[nt >> 1][nt & 1], bl[nt >> 1][2 + (nt & 1)] };
                    mma_bf16(acc[mt][nt], ah[mt], bhp);
                    mma_bf16(acc[mt][nt], ah[mt], blp);
                    mma_bf16(acc[mt][nt], al[mt], bhp);
                }
        }
    }

    const int tr = lane >> 2;
    const int tc = (lane & 3) * 2;
#pragma unroll
    for (int mt = 0; mt < MW; mt++) {
#pragma unroll
        for (int nt = 0; nt < NT_CNT; nt++) {
            int col = n0 + wn + nt * 8 + tc;
            float b0 = bias[col], b1 = bias[col + 1];
#pragma unroll
            for (int half = 0; half < 2; half++) {
                int row = m0 + wm + mt * 16 + tr + half * 8;
                float v0 = acc[mt][nt][half * 2]     + b0;
                float v1 = acc[mt][nt][half * 2 + 1] + b1;
                if (EPI == 1) {
                    v0 = gelu_exact(v0);
                    v1 = gelu_exact(v1);
                    __nv_bfloat16 h0 = __float2bfloat16(v0);
                    __nv_bfloat16 h1 = __float2bfloat16(v1);
                    __nv_bfloat162 hp; hp.x = h0; hp.y = h1;
                    __nv_bfloat162 lp;
                    lp.x = __float2bfloat16(v0 - __bfloat162float(h0));
                    lp.y = __float2bfloat16(v1 - __bfloat162float(h1));
                    *(__nv_bfloat162*)&Ch[(size_t)row * N + col] = hp;
                    *(__nv_bfloat162*)&Cl[(size_t)row * N + col] = lp;
                } else {
                    if (EPI == 2) {
                        float2 rv = *(const float2*)&Res[(size_t)row * N + col];
                        v0 += rv.x; v1 += rv.y;
                    }
                    float2 ov; ov.x = v0; ov.y = v1;
                    *(float2*)&Cf[(size_t)row * N + col] = ov;
                }
            }
        }
    }
}

// ---------------- fused attention: chunk sums + lookback prefix + output ----
__global__ __launch_bounds__(256) void attn_fused_kernel(
    const float* __restrict__ qkv, float* __restrict__ S,
    float* __restrict__ ks, int* __restrict__ flags,
    __nv_bfloat16* __restrict__ oh, __nv_bfloat16* __restrict__ ol)
{
    extern __shared__ float sm[];
    float* Ks   = sm;               // 64 x PS  phi(k)
    float* Vs   = sm + 64  * PS;    // 64 x PS  v
    float* Qs   = sm + 128 * PS;    // 64 x PS  phi(q)
    float* Psh  = sm + 192 * PS;    // 64 x PS  exclusive prefix P[d][e]
    float* As   = sm + 256 * PS;    // 64 x PS  masked QK^T
    float* dens = sm + 320 * PS;    // 64
    float* kps  = dens + 64;        // 64

    const int blk = blockIdx.x;
    const int bh = blk / NCH, c = blk % NCH;
    const int b = bh / HH, h = bh % HH;
    const int tid = threadIdx.x;
    const int d0 = (tid >> 4) * 4, e0 = (tid & 15) * 4;

    // 1. load K (phi) and V
#pragma unroll
    for (int i = tid; i < 4096; i += 256) {
        int t = i >> 6, d = i & 63;
        int row = b * LL + c * CHUNK + t;
        float kv = qkv[row * 768 + 256 + h * 64 + d];
        Ks[t * PS + d] = fmaxf(kv, 0.f) + 1e-6f;
        Vs[t * PS + d] = qkv[row * 768 + 512 + h * 64 + d];
    }
    __syncthreads();

    // 2. own chunk sums -> global, publish flag (release)
    {
        float sc[4][4] = {};
#pragma unroll 4
        for (int t = 0; t < 64; t++) {
            float kd[4], ve[4];
            *(float4*)kd = *(const float4*)&Ks[t * PS + d0];
            *(float4*)ve = *(const float4*)&Vs[t * PS + e0];
#pragma unroll
            for (int i = 0; i < 4; i++)
#pragma unroll
                for (int j = 0; j < 4; j++)
                    sc[i][j] += kd[i] * ve[j];
        }
        float* So = S + (size_t)blk * 4096;
#pragma unroll
        for (int i = 0; i < 4; i++)
            *(float4*)&So[(d0 + i) * 64 + e0] =
                make_float4(sc[i][0], sc[i][1], sc[i][2], sc[i][3]);
        if (tid < 64) {
            float s = 0.f;
#pragma unroll 8
            for (int t = 0; t < 64; t++) s += Ks[t * PS + tid];
            ks[blk * 64 + tid] = s;
        }
    }
    __syncthreads();
    if (tid == 0) { __threadfence(); atomicExch(&flags[blk], 1); }

    // 3. load Q (phi)
#pragma unroll
    for (int i = tid; i < 4096; i += 256) {
        int t = i >> 6, d = i & 63;
        int row = b * LL + c * CHUNK + t;
        float qv = qkv[row * 768 + h * 64 + d];
        Qs[t * PS + d] = fmaxf(qv, 0.f) + 1e-6f;
    }

    // 4. wait for predecessor chunks (acquire)
    if (tid < c) {
        while (atomicAdd(&flags[bh * NCH + tid], 0) == 0) { __nanosleep(60); }
        __threadfence();
    }
    __syncthreads();

    // 5. exclusive prefix
    {
        float pr[4][4] = {};
        for (int cc = 0; cc < c; cc++) {
            const float* Sp = S + (size_t)(bh * NCH + cc) * 4096;
#pragma unroll
            for (int i = 0; i < 4; i++) {
                float4 v = *(const float4*)&Sp[(d0 + i) * 64 + e0];
                pr[i][0] += v.x; pr[i][1] += v.y; pr[i][2] += v.z; pr[i][3] += v.w;
            }
        }
#pragma unroll
        for (int i = 0; i < 4; i++)
            *(float4*)&Psh[(d0 + i) * PS + e0] =
                make_float4(pr[i][0], pr[i][1], pr[i][2], pr[i][3]);
        if (tid < 64) {
            float s = 0.f;
            for (int cc = 0; cc < c; cc++) s += ks[(bh * NCH + cc) * 64 + tid];
            kps[tid] = s;
        }
    }
    __syncthreads();

    const int i0 = d0, j0 = e0;
    float acc[4][4] = {};

    // 6. acc = Q @ P ; den = q . kps
#pragma unroll 2
    for (int d = 0; d < 64; d += 4) {
        float qv[4][4], pv[4][4];
#pragma unroll
        for (int i = 0; i < 4; i++)
            *(float4*)qv[i] = *(const float4*)&Qs[(i0 + i) * PS + d];
#pragma unroll
        for (int dd = 0; dd < 4; dd++)
            *(float4*)pv[dd] = *(const float4*)&Psh[(d + dd) * PS + j0];
#pragma unroll
        for (int i = 0; i < 4; i++)
#pragma unroll
            for (int j = 0; j < 4; j++)
#pragma unroll
                for (int dd = 0; dd < 4; dd++)
                    acc[i][j] += qv[i][dd] * pv[dd][j];
    }
    if (tid < 64) {
        float s = 0.f;
#pragma unroll
        for (int d = 0; d < 64; d += 4) {
            float4 q4 = *(const float4*)&Qs[tid * PS + d];
            float4 k4 = *(const float4*)&kps[d];
            s += q4.x * k4.x + q4.y * k4.y + q4.z * k4.z + q4.w * k4.w;
        }
        dens[tid] = s;
    }

    // 7. A = tril(Q K^T)
    {
        float av[4][4] = {};
#pragma unroll 2
        for (int d = 0; d < 64; d += 4) {
            float qv[4][4], kv[4][4];
#pragma unroll
            for (int i = 0; i < 4; i++)
                *(float4*)qv[i] = *(const float4*)&Qs[(i0 + i) * PS + d];
#pragma unroll
            for (int j = 0; j < 4; j++)
                *(float4*)kv[j] = *(const float4*)&Ks[(j0 + j) * PS + d];
#pragma unroll
            for (int i = 0; i < 4; i++)
#pragma unroll
                for (int j = 0; j < 4; j++)
#pragma unroll
                    for (int dd = 0; dd < 4; dd++)
                        av[i][j] += qv[i][dd] * kv[j][dd];
        }
#pragma unroll
        for (int i = 0; i < 4; i++) {
            float4 o;
            o.x = (j0 + 0 <= i0 + i) ? av[i][0] : 0.f;
            o.y = (j0 + 1 <= i0 + i) ? av[i][1] : 0.f;
            o.z = (j0 + 2 <= i0 + i) ? av[i][2] : 0.f;
            o.w = (j0 + 3 <= i0 + i) ? av[i][3] : 0.f;
            *(float4*)&As[(i0 + i) * PS + j0] = o;
        }
    }
    __syncthreads();

    // 8. den += rowsum(A)
    if (tid < 64) {
        float rs = 0.f;
#pragma unroll
        for (int j = 0; j < 64; j += 4) {
            float4 a4 = *(const float4*)&As[tid * PS + j];
            rs += a4.x + a4.y + a4.z + a4.w;
        }
        dens[tid] += rs;
    }
    __syncthreads();

    // 9. acc += A @ V; write bf16 hi/lo
#pragma unroll 2
    for (int j = 0; j < 64; j += 4) {
        float av[4][4], vv[4][4];
#pragma unroll
        for (int i = 0; i < 4; i++)
            *(float4*)av[i] = *(const float4*)&As[(i0 + i) * PS + j];
#pragma unroll
        for (int m = 0; m < 4; m++)
            *(float4*)vv[m] = *(const float4*)&Vs[(j + m) * PS + j0];
#pragma unroll
        for (int i = 0; i < 4; i++)
#pragma unroll
            for (int jj = 0; jj < 4; jj++)
#pragma unroll
                for (int m = 0; m < 4; m++)
                    acc[i][jj] += av[i][m] * vv[m][jj];
    }

#pragma unroll
    for (int i = 0; i < 4; i++) {
        float dn = fmaxf(dens[i0 + i], 1e-6f);
        int row = b * LL + c * CHUNK + i0 + i;
        float inv = 1.0f / dn;
        size_t idx = (size_t)row * EE + h * 64 + j0;
        __nv_bfloat162 hp0, hp1, lp0, lp1;
        float v0 = acc[i][0] * inv, v1 = acc[i][1] * inv;
        float v2 = acc[i][2] * inv, v3 = acc[i][3] * inv;
        __nv_bfloat16 h0 = __float2bfloat16(v0), h1 = __float2bfloat16(v1);
        __nv_bfloat16 h2 = __float2bfloat16(v2), h3 = __float2bfloat16(v3);
        hp0.x = h0; hp0.y = h1; hp1.x = h2; hp1.y = h3;
        lp0.x = __float2bfloat16(v0 - __bfloat162float(h0));
        lp0.y = __float2bfloat16(v1 - __bfloat162float(h1));
        lp1.x = __float2bfloat16(v2 - __bfloat162float(h2));
        lp1.y = __float2bfloat16(v3 - __bfloat162float(h3));
        uint2 hh, ll;
        hh.x = *(uint32_t*)&hp0; hh.y = *(uint32_t*)&hp1;
        ll.x = *(uint32_t*)&lp0; ll.y = *(uint32_t*)&lp1;
        *(uint2*)&oh[idx] = hh;
        *(uint2*)&ol[idx] = ll;
    }
}

// ---------------- final LN + pred fused -------------------------------------
__global__ __launch_bounds__(256) void predln_kernel(
    const float* __restrict__ x, const float* __restrict__ g,
    const float* __restrict__ bta,
    const float* __restrict__ pred_w, const float* __restrict__ pred_b,
    float* __restrict__ out)
{
    int bk = blockIdx.x;
    int b = bk / KSTEP, k = bk % KSTEP;
    int row = b * LL + 3 * k + 1;
    int e = threadIdx.x;
    __shared__ float red[8];
    __shared__ float ys[EE];

    float v = x[(size_t)row * EE + e];
    float s = v;
#pragma unroll
    for (int o = 16; o; o >>= 1) s += __shfl_xor_sync(0xffffffffu, s, o);
    if ((e & 31) == 0) red[e >> 5] = s;
    __syncthreads();
    if (e < 8) {
        float t = red[e];
#pragma unroll
        for (int o = 4; o; o >>= 1) t += __shfl_xor_sync(0xffu, t, o);
        if (e == 0) red[0] = t;
    }
    __syncthreads();
    float mean = red[0] * (1.0f / EE);
    __syncthreads();
    float d = v - mean;
    float s2 = d * d;
#pragma unroll
    for (int o = 16; o; o >>= 1) s2 += __shfl_xor_sync(0xffffffffu, s2, o);
    if ((e & 31) == 0) red[e >> 5] = s2;
    __syncthreads();
    if (e < 8) {
        float t = red[e];
#pragma unroll
        for (int o = 4; o; o >>= 1) t += __shfl_xor_sync(0xffu, t, o);
        if (e == 0) red[0] = t;
    }
    __syncthreads();
    float var = red[0] * (1.0f / EE);
    float r = rsqrtf(var + 1e-5f);
    ys[e] = d * r * g[e] + bta[e];
    __syncthreads();

    int w = e >> 5, lane = e & 31;
    if (w < NACT) {
        float sum = 0.f;
        for (int i = lane; i < EE; i += 32) sum += ys[i] * pred_w[i * NACT + w];
#pragma unroll
        for (int o = 16; o; o >>= 1) sum += __shfl_xor_sync(0xffffffffu, sum, o);
        if (lane == 0) out[bk * NACT + w] = sum + pred_b[w];
    }
}

// ---------------- launch ----------------------------------------------------
extern "C" void kernel_launch(void* const* d_in, const int* in_sizes, int n_in,
                              void* d_out, int out_size)
{
    const float* rtg      = (const float*)d_in[0];
    const float* state    = (const float*)d_in[1];
    const float* action   = (const float*)d_in[2];
    const float* rtg_w    = (const float*)d_in[3];
    const float* rtg_b    = (const float*)d_in[4];
    const float* state_w  = (const float*)d_in[5];
    const float* state_b  = (const float*)d_in[6];
    const float* action_w = (const float*)d_in[7];
    const float* action_b = (const float*)d_in[8];
    const float* pos_emb  = (const float*)d_in[9];
    const float* norm1_g  = (const float*)d_in[10];
    const float* norm1_b  = (const float*)d_in[11];
    const float* qkv_w    = (const float*)d_in[12];
    const float* qkv_b    = (const float*)d_in[13];
    const float* out_w    = (const float*)d_in[14];
    const float* out_b    = (const float*)d_in[15];
    const float* norm2_g  = (const float*)d_in[16];
    const float* norm2_b  = (const float*)d_in[17];
    const float* ffn1_w   = (const float*)d_in[18];
    const float* ffn1_b   = (const float*)d_in[19];
    const float* ffn2_w   = (const float*)d_in[20];
    const float* ffn2_b   = (const float*)d_in[21];
    const float* normf_g  = (const float*)d_in[22];
    const float* normf_b  = (const float*)d_in[23];
    const float* pred_w   = (const float*)d_in[24];
    const float* pred_b   = (const float*)d_in[25];

    float *x, *xn, *qkv, *S, *ks;
    int* flags;
    __nv_bfloat16 *xh, *xl, *oh, *ol, *ffh, *ffl, *wh, *wl;
    cudaGetSymbolAddress((void**)&x,     g_x);
    cudaGetSymbolAddress((void**)&xn,    g_xn);
    cudaGetSymbolAddress((void**)&qkv,   g_qkv);
    cudaGetSymbolAddress((void**)&S,     g_S);
    cudaGetSymbolAddress((void**)&ks,    g_ks);
    cudaGetSymbolAddress((void**)&flags, g_flag);
    cudaGetSymbolAddress((void**)&xh,    g_xh);
    cudaGetSymbolAddress((void**)&xl,    g_xl);
    cudaGetSymbolAddress((void**)&oh,    g_oh);
    cudaGetSymbolAddress((void**)&ol,    g_ol);
    cudaGetSymbolAddress((void**)&ffh,   g_ffh);
    cudaGetSymbolAddress((void**)&ffl,   g_ffl);
    cudaGetSymbolAddress((void**)&wh,    g_wh);
    cudaGetSymbolAddress((void**)&wl,    g_wl);

    const int SMEM_ATT  = (320 * PS + 128) * sizeof(float);        // 87552
    const int SMEM_G128 = 2 * (2 * 128 * 72 * 2 + 2 * 64 * 72 * 2); // 110592
    const int SMEM_G32  = 2 * (2 * 32 * 72 * 2 + 2 * 64 * 72 * 2);  // 55296
    cudaFuncSetAttribute(attn_fused_kernel,
                         cudaFuncAttributeMaxDynamicSharedMemorySize, SMEM_ATT);
    cudaFuncSetAttribute((const void*)gemm_mma_kernel<128, 0>,
                         cudaFuncAttributeMaxDynamicSharedMemorySize, SMEM_G128);
    cudaFuncSetAttribute((const void*)gemm_mma_kernel<128, 1>,
                         cudaFuncAttributeMaxDynamicSharedMemorySize, SMEM_G128);
    cudaFuncSetAttribute((const void*)gemm_mma_kernel<32, 2>,
                         cudaFuncAttributeMaxDynamicSharedMemorySize, SMEM_G32);

    prep_kernel<<<dim3(32, 32, 11), 256>>>(
        qkv_w, out_w, ffn1_w, ffn2_w, wh, wl,
        rtg, state, action, rtg_w, rtg_b, state_w, state_b,
        action_w, action_b, pos_emb, norm1_g, norm1_b, x, xh, xl);

    for (int layer = 0; layer < NLAYER; layer++) {
        const float* n2g = norm2_g + layer * EE;
        const float* n2b = norm2_b + layer * EE;
        const float* qb  = qkv_b  + layer * 3 * EE;
        const float* ob  = out_b  + layer * EE;
        const float* f1b = ffn1_b + layer * FFD;
        const float* f2b = ffn2_b + layer * EE;
        size_t qoff  = (size_t)layer * 196608;
        size_t ooff  = 393216  + (size_t)layer * 65536;
        size_t f1off = 524288  + (size_t)layer * 262144;
        size_t f2off = 1048576 + (size_t)layer * 262144;
        int* lflags = flags + layer * NBH * NCH;

        if (layer > 0) {
            ln4_kernel<<<MTOK / 4, 256>>>(x, norm1_g + layer * EE, norm1_b + layer * EE,
                                          xn, xh, xl);
        }

        gemm_mma_kernel<128, 0><<<dim3(12, 24), 256, SMEM_G128>>>(
            xh, xl, wh + qoff, wl + qoff, qb, nullptr, qkv, nullptr, nullptr,
            768, 256, lflags);

        attn_fused_kernel<<<NBH * NCH, 256, SMEM_ATT>>>(qkv, S, ks, lflags, oh, ol);

        // out proj: MT=32 tiles -> 384 blocks
        gemm_mma_kernel<32, 2><<<dim3(4, 96), 256, SMEM_G32>>>(
            oh, ol, wh + ooff, wl + ooff, ob, x, x, nullptr, nullptr,
            256, 256, nullptr);

        ln4_kernel<<<MTOK / 4, 256>>>(x, n2g, n2b, xn, xh, xl);

        gemm_mma_kernel<128, 1><<<dim3(16, 24), 256, SMEM_G128>>>(
            xh, xl, wh + f1off, wl + f1off, f1b, nullptr, nullptr, ffh, ffl,
            1024, 256, nullptr);

        // ffn2: MT=32 tiles -> 384 blocks
        gemm_mma_kernel<32, 2><<<dim3(4, 96), 256, SMEM_G32>>>(
            ffh, ffl, wh + f2off, wl + f2off, f2b, x, x, nullptr, nullptr,
            256, 1024, nullptr);
    }

    predln_kernel<<<BB * KSTEP, 256>>>(x, normf_g, normf_b, pred_w, pred_b,
                                       (float*)d_out);
}